// round 1
// baseline (speedup 1.0000x reference)
#include <cuda_runtime.h>
#include <math.h>

#define B_ 4
#define S_ 2048
#define D_ 1024
#define F_ 4096

__device__ float g_scores[(size_t)B_ * S_ * S_];
__device__ float g_attn  [(size_t)B_ * S_ * D_];
__device__ float g_h1    [(size_t)B_ * S_ * D_];
__device__ float g_ffn1  [(size_t)B_ * S_ * F_];
__device__ float g_ffn2  [(size_t)B_ * S_ * D_];

__device__ __forceinline__ float warpSum(float v) {
#pragma unroll
    for (int o = 16; o > 0; o >>= 1) v += __shfl_xor_sync(0xFFFFFFFFu, v, o);
    return v;
}
__device__ __forceinline__ float warpMax(float v) {
#pragma unroll
    for (int o = 16; o > 0; o >>= 1) v = fmaxf(v, __shfl_xor_sync(0xFFFFFFFFu, v, o));
    return v;
}
__device__ __forceinline__ float blockSum(float v) {
    __shared__ float sh[9];
    __syncthreads();
    int lane = threadIdx.x & 31, w = threadIdx.x >> 5;
    v = warpSum(v);
    if (lane == 0) sh[w] = v;
    __syncthreads();
    if (w == 0) {
        float x = (lane < 8) ? sh[lane] : 0.0f;
        x = warpSum(x);
        if (lane == 0) sh[8] = x;
    }
    __syncthreads();
    return sh[8];
}
__device__ __forceinline__ float blockMax(float v) {
    __shared__ float sh[9];
    __syncthreads();
    int lane = threadIdx.x & 31, w = threadIdx.x >> 5;
    v = warpMax(v);
    if (lane == 0) sh[w] = v;
    __syncthreads();
    if (w == 0) {
        float x = (lane < 8) ? sh[lane] : -INFINITY;
        x = warpMax(x);
        if (lane == 0) sh[8] = x;
    }
    __syncthreads();
    return sh[8];
}

// C[M,N] = A[M,K] x B.  TRANSB: B is [N,K] (C=A*B^T), else B is [K,N].
// EPI: 0 = *alpha ; 1 = +bias then exact GELU ; 2 = +bias.
template <bool TRANSB, int EPI>
__global__ __launch_bounds__(256)
void gemm_kernel(const float* __restrict__ A, const float* __restrict__ Bm,
                 const float* __restrict__ bias, float* __restrict__ C,
                 int M, int N, int K,
                 size_t sA, size_t sB, size_t sC, float alpha) {
    __shared__ float As[16][128];
    __shared__ float Bs[16][128];

    const int z = blockIdx.z;
    A  += (size_t)z * sA;
    Bm += (size_t)z * sB;
    C  += (size_t)z * sC;

    const int m0 = blockIdx.y * 128;
    const int n0 = blockIdx.x * 128;
    const int tid = threadIdx.x;
    const int tx = tid & 15;
    const int ty = tid >> 4;

    float acc[8][8];
#pragma unroll
    for (int i = 0; i < 8; i++)
#pragma unroll
        for (int j = 0; j < 8; j++) acc[i][j] = 0.0f;

    for (int k0 = 0; k0 < K; k0 += 16) {
#pragma unroll
        for (int i = 0; i < 2; i++) {
            int lin = tid + i * 256;
            int row = lin >> 2;
            int kq  = (lin & 3) * 4;
            float4 v = *(const float4*)(A + (size_t)(m0 + row) * K + k0 + kq);
            As[kq + 0][row] = v.x;
            As[kq + 1][row] = v.y;
            As[kq + 2][row] = v.z;
            As[kq + 3][row] = v.w;
        }
        if (TRANSB) {
#pragma unroll
            for (int i = 0; i < 2; i++) {
                int lin = tid + i * 256;
                int row = lin >> 2;
                int kq  = (lin & 3) * 4;
                float4 v = *(const float4*)(Bm + (size_t)(n0 + row) * K + k0 + kq);
                Bs[kq + 0][row] = v.x;
                Bs[kq + 1][row] = v.y;
                Bs[kq + 2][row] = v.z;
                Bs[kq + 3][row] = v.w;
            }
        } else {
#pragma unroll
            for (int i = 0; i < 2; i++) {
                int lin = tid + i * 256;
                int kk = lin >> 5;
                int ng = (lin & 31) * 4;
                *(float4*)&Bs[kk][ng] =
                    *(const float4*)(Bm + (size_t)(k0 + kk) * N + n0 + ng);
            }
        }
        __syncthreads();

#pragma unroll
        for (int kk = 0; kk < 16; kk++) {
            float a[8], b[8];
            *(float4*)&a[0] = *(float4*)&As[kk][ty * 8];
            *(float4*)&a[4] = *(float4*)&As[kk][ty * 8 + 4];
            *(float4*)&b[0] = *(float4*)&Bs[kk][tx * 8];
            *(float4*)&b[4] = *(float4*)&Bs[kk][tx * 8 + 4];
#pragma unroll
            for (int i = 0; i < 8; i++)
#pragma unroll
                for (int j = 0; j < 8; j++) acc[i][j] += a[i] * b[j];
        }
        __syncthreads();
    }

#pragma unroll
    for (int i = 0; i < 8; i++) {
        int m = m0 + ty * 8 + i;
        float* crow = C + (size_t)m * N + n0 + tx * 8;
#pragma unroll
        for (int j = 0; j < 8; j++) {
            float x = acc[i][j];
            if (EPI == 0) {
                x *= alpha;
            } else {
                x += bias[n0 + tx * 8 + j];
                if (EPI == 1)
                    x = 0.5f * x * (1.0f + erff(x * 0.70710678118654752f));
            }
            acc[i][j] = x;
        }
        *(float4*)(crow)     = *(float4*)&acc[i][0];
        *(float4*)(crow + 4) = *(float4*)&acc[i][4];
    }
}

__global__ __launch_bounds__(256)
void softmax_kernel(float* __restrict__ scores, const float* __restrict__ mask) {
    const int row = blockIdx.x;
    const int b = row / S_;
    float* p = scores + (size_t)row * S_;
    const float* mk = mask + (size_t)b * S_;
    const int t = threadIdx.x;

    float v[8];
    float mx = -INFINITY;
#pragma unroll
    for (int i = 0; i < 8; i++) {
        int k = t + i * 256;
        v[i] = p[k] + mk[k];
        mx = fmaxf(mx, v[i]);
    }
    mx = blockMax(mx);
    float s = 0.0f;
#pragma unroll
    for (int i = 0; i < 8; i++) {
        v[i] = __expf(v[i] - mx);
        s += v[i];
    }
    s = blockSum(s);
    float inv = 1.0f / s;
#pragma unroll
    for (int i = 0; i < 8; i++) p[t + i * 256] = v[i] * inv;
}

__global__ __launch_bounds__(256)
void add_ln_kernel(const float* __restrict__ x, const float* __restrict__ res,
                   const float* __restrict__ gamma, const float* __restrict__ beta,
                   float* __restrict__ out) {
    const int row = blockIdx.x;
    const float* px = x + (size_t)row * D_;
    const float* pr = res + (size_t)row * D_;
    float* po = out + (size_t)row * D_;
    const int t = threadIdx.x;

    float v[4];
    float s = 0.0f, s2 = 0.0f;
#pragma unroll
    for (int i = 0; i < 4; i++) {
        int k = t + i * 256;
        v[i] = px[k] + pr[k];
        s += v[i];
        s2 += v[i] * v[i];
    }
    s  = blockSum(s);
    s2 = blockSum(s2);
    const float mu  = s * (1.0f / D_);
    const float var = s2 * (1.0f / D_) - mu * mu;
    const float inv = rsqrtf(var + 1e-5f);
#pragma unroll
    for (int i = 0; i < 4; i++) {
        int k = t + i * 256;
        po[k] = (v[i] - mu) * inv * gamma[k] + beta[k];
    }
}

extern "C" void kernel_launch(void* const* d_in, const int* in_sizes, int n_in,
                              void* d_out, int out_size) {
    const float* h    = (const float*)d_in[0];
    const float* mask = (const float*)d_in[1];
    const float* w1   = (const float*)d_in[2];
    const float* b1   = (const float*)d_in[3];
    const float* w2   = (const float*)d_in[4];
    const float* b2   = (const float*)d_in[5];
    const float* g1   = (const float*)d_in[6];
    const float* be1  = (const float*)d_in[7];
    const float* g2   = (const float*)d_in[8];
    const float* be2  = (const float*)d_in[9];
    float* out = (float*)d_out;

    float *scores, *attn, *h1, *f1, *f2;
    cudaGetSymbolAddress((void**)&scores, g_scores);
    cudaGetSymbolAddress((void**)&attn,   g_attn);
    cudaGetSymbolAddress((void**)&h1,     g_h1);
    cudaGetSymbolAddress((void**)&f1,     g_ffn1);
    cudaGetSymbolAddress((void**)&f2,     g_ffn2);

    const size_t SD = (size_t)S_ * D_;
    const size_t SS = (size_t)S_ * S_;

    // 1) scores = (h @ h^T) / sqrt(D)   (batched NT GEMM)
    gemm_kernel<true, 0><<<dim3(S_ / 128, S_ / 128, B_), 256>>>(
        h, h, nullptr, scores, S_, S_, D_, SD, SD, SS, 0.03125f);

    // 2) softmax over rows (+ additive mask)
    softmax_kernel<<<B_ * S_, 256>>>(scores, mask);

    // 3) attn = probs @ h   (batched NN GEMM)
    gemm_kernel<false, 0><<<dim3(D_ / 128, S_ / 128, B_), 256>>>(
        scores, h, nullptr, attn, S_, D_, S_, SS, SD, SD, 1.0f);

    // 4) h1 = LN1(h + attn)
    add_ln_kernel<<<B_ * S_, 256>>>(attn, h, g1, be1, h1);

    // 5) f1 = GELU(h1 @ w1 + b1)   M=8192 N=4096 K=1024
    gemm_kernel<false, 1><<<dim3(F_ / 128, (B_ * S_) / 128, 1), 256>>>(
        h1, w1, b1, f1, B_ * S_, F_, D_, 0, 0, 0, 1.0f);

    // 6) f2 = f1 @ w2 + b2         M=8192 N=1024 K=4096
    gemm_kernel<false, 2><<<dim3(D_ / 128, (B_ * S_) / 128, 1), 256>>>(
        f1, w2, b2, f2, B_ * S_, D_, F_, 0, 0, 0, 1.0f);

    // 7) out = LN2(h1 + f2)
    add_ln_kernel<<<B_ * S_, 256>>>(f2, h1, g2, be2, out);
}

// round 3
// speedup vs baseline: 3.0067x; 3.0067x over previous
#include <cuda_runtime.h>
#include <math.h>
#include <stdint.h>

#define B_ 4
#define S_ 2048
#define D_ 1024
#define F_ 4096

// ---------------- scratch (static device globals; no allocs) ----------------
__device__ float g_scores[(size_t)B_ * S_ * S_];   // 64 MB
__device__ float g_attn  [(size_t)B_ * S_ * D_];   // 32 MB
__device__ float g_h1    [(size_t)B_ * S_ * D_];   // 32 MB (fp32 residual)
__device__ float g_h1r   [(size_t)B_ * S_ * D_];   // 32 MB (tf32-rounded)
__device__ float g_f1    [(size_t)B_ * S_ * F_];   // 128 MB
__device__ float g_f2    [(size_t)B_ * S_ * D_];   // 32 MB
__device__ float g_hr    [(size_t)B_ * S_ * D_];   // 32 MB rounded h
__device__ float g_hT    [(size_t)B_ * D_ * S_];   // 32 MB h^T (rounded)
__device__ float g_w1T   [(size_t)F_ * D_];        // 16 MB
__device__ float g_w2T   [(size_t)D_ * F_];        // 16 MB

// ---------------- helpers ----------------
__device__ __forceinline__ uint32_t smem_u32(const void* p) {
    return (uint32_t)__cvta_generic_to_shared(p);
}
__device__ __forceinline__ float tf32r(float x) {  // round-to-nearest tf32
    uint32_t u;
    asm("cvt.rna.tf32.f32 %0, %1;" : "=r"(u) : "f"(x));
    return __uint_as_float(u);
}

#define CP_ASYNC16(sa, ga) \
    asm volatile("cp.async.cg.shared.global [%0], [%1], 16;" :: "r"(sa), "l"(ga))
#define CP_COMMIT() asm volatile("cp.async.commit_group;" ::: "memory")
#define CP_WAIT1()  asm volatile("cp.async.wait_group 1;" ::: "memory")

// m16n8k8 tf32 MMA (legacy path — supported on bare sm_103)
__device__ __forceinline__ void mma_tf32(float* d, const uint32_t* a, const uint32_t* b) {
    asm volatile(
        "mma.sync.aligned.m16n8k8.row.col.f32.tf32.tf32.f32 "
        "{%0,%1,%2,%3}, {%4,%5,%6,%7}, {%8,%9}, {%0,%1,%2,%3};"
        : "+f"(d[0]), "+f"(d[1]), "+f"(d[2]), "+f"(d[3])
        : "r"(a[0]), "r"(a[1]), "r"(a[2]), "r"(a[3]), "r"(b[0]), "r"(b[1]));
}

// ---------------- tf32 GEMM ----------------
// C[M,N] = A[M,K] * B_op[N,K]^T. Both operands K-major fp32, pre-rounded tf32.
// CTA tile 128x128, K-chunk 32, 3-stage cp.async pipeline.
// SMEM tiles padded to 36 floats/row (36 = 4 mod 32 -> conflict-free fragments).
// EPI: 0 = *alpha ; 1 = +bias, exact GELU, tf32-round ; 2 = +bias.
#define KC 32
#define LDT 36
#define TILE_BYTES (128 * LDT * 4)        // 18432
#define STAGE_BYTES (2 * TILE_BYTES)      // 36864 (A + B)
#define NSTAGE 3
#define DYN_SMEM (NSTAGE * STAGE_BYTES)   // 110592

__device__ __forceinline__ void load_tile(uint32_t sbase, const float* __restrict__ Arow,
                                          const float* __restrict__ Brow,
                                          int K, int kc, int tid) {
    const int r0  = tid >> 3;           // 0..31
    const int c4  = (tid & 7) * 4;      // float offset within 32
    const int c16 = (tid & 7) * 16;     // byte offset
    const float* Ap = Arow + (size_t)kc * KC + c4;
    const float* Bp = Brow + (size_t)kc * KC + c4;
#pragma unroll
    for (int i = 0; i < 4; i++) {
        int r = r0 + i * 32;
        CP_ASYNC16(sbase + r * (LDT * 4) + c16, Ap + (size_t)r * K);
    }
    uint32_t bb = sbase + TILE_BYTES;
#pragma unroll
    for (int i = 0; i < 4; i++) {
        int r = r0 + i * 32;
        CP_ASYNC16(bb + r * (LDT * 4) + c16, Bp + (size_t)r * K);
    }
}

template <int EPI>
__global__ __launch_bounds__(256, 1)
void mma_gemm(const float* __restrict__ A, const float* __restrict__ Bm,
              const float* __restrict__ bias, float* __restrict__ C,
              int M, int N, int K, size_t sA, size_t sB, size_t sC, float alpha) {
    extern __shared__ char dsm[];
    const int tid = threadIdx.x, wid = tid >> 5, lane = tid & 31;
    const int z = blockIdx.z;
    A  += (size_t)z * sA;
    Bm += (size_t)z * sB;
    C  += (size_t)z * sC;
    const int m0 = blockIdx.y * 128;
    const int n0 = blockIdx.x * 128;
    const float* Arow = A + (size_t)m0 * K;
    const float* Brow = Bm + (size_t)n0 * K;
    const int NC = K / KC;

    // warp tile: 32(m) x 64(n); warps 4(m) x 2(n)
    const int wm = (wid & 3) * 32;
    const int wn = (wid >> 2) * 64;
    const int gq = lane >> 2;      // group id (0..7)
    const int tg = lane & 3;       // thread in group

    float acc[2][8][4];
#pragma unroll
    for (int i = 0; i < 2; i++)
#pragma unroll
        for (int j = 0; j < 8; j++)
#pragma unroll
            for (int q = 0; q < 4; q++) acc[i][j][q] = 0.0f;

    const uint32_t s0 = smem_u32(dsm);
    // prologue: stages 0,1
    load_tile(s0, Arow, Brow, K, 0, tid);
    CP_COMMIT();
    load_tile(s0 + STAGE_BYTES, Arow, Brow, K, 1, tid);
    CP_COMMIT();

    int buf = 0;
    for (int k = 0; k < NC; k++) {
        CP_WAIT1();          // group k complete
        __syncthreads();     // visible to all warps; prior compute done
        if (k + 2 < NC) {
            int nb = buf + 2;
            if (nb >= NSTAGE) nb -= NSTAGE;
            load_tile(s0 + nb * STAGE_BYTES, Arow, Brow, K, k + 2, tid);
        }
        CP_COMMIT();

        const uint32_t* As = (const uint32_t*)(dsm + buf * STAGE_BYTES);
        const uint32_t* Bs = (const uint32_t*)(dsm + buf * STAGE_BYTES + TILE_BYTES);
        // per-warp fragment base rows
        const uint32_t* a_lo = As + (wm + gq) * LDT + tg;       // rows wm+gq (+8,+16,+24)
        const uint32_t* b_lo = Bs + (wn + gq) * LDT + tg;       // n rows wn+gq + j*8

#pragma unroll
        for (int ks = 0; ks < 4; ks++) {
            const int kb = ks * 8;
            uint32_t afr[2][4];
#pragma unroll
            for (int i = 0; i < 2; i++) {
                const uint32_t* p = a_lo + i * 16 * LDT + kb;
                afr[i][0] = p[0];
                afr[i][1] = p[8 * LDT];
                afr[i][2] = p[4];
                afr[i][3] = p[8 * LDT + 4];
            }
            uint32_t bfr[8][2];
#pragma unroll
            for (int j = 0; j < 8; j++) {
                const uint32_t* p = b_lo + j * 8 * LDT + kb;
                bfr[j][0] = p[0];
                bfr[j][1] = p[4];
            }
#pragma unroll
            for (int i = 0; i < 2; i++)
#pragma unroll
                for (int j = 0; j < 8; j++) mma_tf32(acc[i][j], afr[i], bfr[j]);
        }
        buf++;
        if (buf == NSTAGE) buf = 0;
        __syncthreads();
    }

    // epilogue: direct stores (float2 per row-pair fragment)
#pragma unroll
    for (int i = 0; i < 2; i++) {
        const int rb = m0 + wm + i * 16 + gq;
#pragma unroll
        for (int j = 0; j < 8; j++) {
            const int cb = n0 + wn + j * 8 + tg * 2;
            float bx = 0.f, by = 0.f;
            if (EPI != 0) { bx = bias[cb]; by = bias[cb + 1]; }
#pragma unroll
            for (int h = 0; h < 2; h++) {   // row, row+8
                float x = acc[i][j][h * 2 + 0];
                float y = acc[i][j][h * 2 + 1];
                if (EPI == 0) {
                    x *= alpha; y *= alpha;
                } else {
                    x += bx; y += by;
                    if (EPI == 1) {
                        x = tf32r(0.5f * x * (1.0f + erff(x * 0.7071067811865475f)));
                        y = tf32r(0.5f * y * (1.0f + erff(y * 0.7071067811865475f)));
                    }
                }
                *(float2*)(C + (size_t)(rb + h * 8) * N + cb) = make_float2(x, y);
            }
        }
    }
}

// ---------------- pointwise / reduction kernels ----------------
__device__ __forceinline__ float warpSum(float v) {
#pragma unroll
    for (int o = 16; o > 0; o >>= 1) v += __shfl_xor_sync(0xFFFFFFFFu, v, o);
    return v;
}
__device__ __forceinline__ float warpMax(float v) {
#pragma unroll
    for (int o = 16; o > 0; o >>= 1) v = fmaxf(v, __shfl_xor_sync(0xFFFFFFFFu, v, o));
    return v;
}
__device__ __forceinline__ float blockSum(float v) {
    __shared__ float sh[9];
    __syncthreads();
    int lane = threadIdx.x & 31, w = threadIdx.x >> 5;
    v = warpSum(v);
    if (lane == 0) sh[w] = v;
    __syncthreads();
    if (w == 0) {
        float x = (lane < 8) ? sh[lane] : 0.0f;
        x = warpSum(x);
        if (lane == 0) sh[8] = x;
    }
    __syncthreads();
    return sh[8];
}
__device__ __forceinline__ float blockMax(float v) {
    __shared__ float sh[9];
    __syncthreads();
    int lane = threadIdx.x & 31, w = threadIdx.x >> 5;
    v = warpMax(v);
    if (lane == 0) sh[w] = v;
    __syncthreads();
    if (w == 0) {
        float x = (lane < 8) ? sh[lane] : -INFINITY;
        x = warpMax(x);
        if (lane == 0) sh[8] = x;
    }
    __syncthreads();
    return sh[8];
}

__global__ __launch_bounds__(256)
void softmax_kernel(float* __restrict__ scores, const float* __restrict__ mask) {
    const int row = blockIdx.x;
    const int b = row / S_;
    float* p = scores + (size_t)row * S_;
    const float* mk = mask + (size_t)b * S_;
    const int t = threadIdx.x;
    float v[8];
    float mx = -INFINITY;
#pragma unroll
    for (int i = 0; i < 8; i++) {
        int k = t + i * 256;
        v[i] = p[k] + mk[k];
        mx = fmaxf(mx, v[i]);
    }
    mx = blockMax(mx);
    float s = 0.0f;
#pragma unroll
    for (int i = 0; i < 8; i++) {
        v[i] = __expf(v[i] - mx);
        s += v[i];
    }
    s = blockSum(s);
    float inv = 1.0f / s;
#pragma unroll
    for (int i = 0; i < 8; i++) p[t + i * 256] = tf32r(v[i] * inv);  // feeds tf32 GEMM
}

__global__ __launch_bounds__(256)
void add_ln_kernel(const float* __restrict__ x, const float* __restrict__ res,
                   const float* __restrict__ gamma, const float* __restrict__ beta,
                   float* __restrict__ out, float* __restrict__ out_r) {
    const int row = blockIdx.x;
    const float* px = x + (size_t)row * D_;
    const float* pr = res + (size_t)row * D_;
    float* po = out + (size_t)row * D_;
    const int t = threadIdx.x;
    float v[4];
    float s = 0.0f, s2 = 0.0f;
#pragma unroll
    for (int i = 0; i < 4; i++) {
        int k = t + i * 256;
        v[i] = px[k] + pr[k];
        s += v[i];
        s2 += v[i] * v[i];
    }
    s = blockSum(s);
    s2 = blockSum(s2);
    const float mu = s * (1.0f / D_);
    const float var = s2 * (1.0f / D_) - mu * mu;
    const float inv = rsqrtf(var + 1e-5f);
#pragma unroll
    for (int i = 0; i < 4; i++) {
        int k = t + i * 256;
        float y = (v[i] - mu) * inv * gamma[k] + beta[k];
        po[k] = y;
        if (out_r) out_r[(size_t)row * D_ + k] = tf32r(y);
    }
}

// dst[c,r] = round_tf32(src[r,c]); batched by z with strides.
__global__ __launch_bounds__(256)
void transpose_kernel(const float* __restrict__ src, float* __restrict__ dst,
                      int R, int C, size_t sS, size_t sD) {
    __shared__ float t[32][33];
    src += (size_t)blockIdx.z * sS;
    dst += (size_t)blockIdx.z * sD;
    const int c0 = blockIdx.x * 32, r0 = blockIdx.y * 32;
    const int x = threadIdx.x & 31, y = (threadIdx.x >> 5) * 4;
#pragma unroll
    for (int i = 0; i < 4; i++)
        t[y + i][x] = src[(size_t)(r0 + y + i) * C + c0 + x];
    __syncthreads();
#pragma unroll
    for (int i = 0; i < 4; i++)
        dst[(size_t)(c0 + y + i) * R + r0 + x] = tf32r(t[x][y + i]);
}

__global__ __launch_bounds__(256)
void round_copy_kernel(const float* __restrict__ src, float* __restrict__ dst, size_t n4) {
    size_t i = (size_t)blockIdx.x * 256 + threadIdx.x;
    if (i < n4) {
        float4 v = ((const float4*)src)[i];
        v.x = tf32r(v.x); v.y = tf32r(v.y); v.z = tf32r(v.z); v.w = tf32r(v.w);
        ((float4*)dst)[i] = v;
    }
}

// ---------------- launch ----------------
extern "C" void kernel_launch(void* const* d_in, const int* in_sizes, int n_in,
                              void* d_out, int out_size) {
    const float* h    = (const float*)d_in[0];
    const float* mask = (const float*)d_in[1];
    const float* w1   = (const float*)d_in[2];
    const float* b1   = (const float*)d_in[3];
    const float* w2   = (const float*)d_in[4];
    const float* b2   = (const float*)d_in[5];
    const float* g1   = (const float*)d_in[6];
    const float* be1  = (const float*)d_in[7];
    const float* g2   = (const float*)d_in[8];
    const float* be2  = (const float*)d_in[9];
    float* out = (float*)d_out;

    float *scores, *attn, *h1, *h1r, *f1, *f2, *hr, *hT, *w1T, *w2T;
    cudaGetSymbolAddress((void**)&scores, g_scores);
    cudaGetSymbolAddress((void**)&attn, g_attn);
    cudaGetSymbolAddress((void**)&h1, g_h1);
    cudaGetSymbolAddress((void**)&h1r, g_h1r);
    cudaGetSymbolAddress((void**)&f1, g_f1);
    cudaGetSymbolAddress((void**)&f2, g_f2);
    cudaGetSymbolAddress((void**)&hr, g_hr);
    cudaGetSymbolAddress((void**)&hT, g_hT);
    cudaGetSymbolAddress((void**)&w1T, g_w1T);
    cudaGetSymbolAddress((void**)&w2T, g_w2T);

    cudaFuncSetAttribute(mma_gemm<0>, cudaFuncAttributeMaxDynamicSharedMemorySize, DYN_SMEM);
    cudaFuncSetAttribute(mma_gemm<1>, cudaFuncAttributeMaxDynamicSharedMemorySize, DYN_SMEM);
    cudaFuncSetAttribute(mma_gemm<2>, cudaFuncAttributeMaxDynamicSharedMemorySize, DYN_SMEM);

    const size_t SD = (size_t)S_ * D_;
    const size_t SS = (size_t)S_ * S_;

    // operand prep: tf32 rounding + K-major transposes
    round_copy_kernel<<<(B_ * SD / 4 + 255) / 256, 256>>>(h, hr, B_ * SD / 4);
    transpose_kernel<<<dim3(D_ / 32, S_ / 32, B_), 256>>>(h, hT, S_, D_, SD, SD);
    transpose_kernel<<<dim3(F_ / 32, D_ / 32, 1), 256>>>(w1, w1T, D_, F_, 0, 0);
    transpose_kernel<<<dim3(D_ / 32, F_ / 32, 1), 256>>>(w2, w2T, F_, D_, 0, 0);

    // 1) scores = (h @ h^T) / 32
    mma_gemm<0><<<dim3(S_ / 128, S_ / 128, B_), 256, DYN_SMEM>>>(
        hr, hr, nullptr, scores, S_, S_, D_, SD, SD, SS, 0.03125f);

    // 2) softmax (+mask), tf32-rounded
    softmax_kernel<<<B_ * S_, 256>>>(scores, mask);

    // 3) attn = P @ h   (B_op = h^T, K-major)
    mma_gemm<0><<<dim3(D_ / 128, S_ / 128, B_), 256, DYN_SMEM>>>(
        scores, hT, nullptr, attn, S_, D_, S_, SS, SD, SD, 1.0f);

    // 4) h1 = LN1(h + attn)  (+ rounded twin)
    add_ln_kernel<<<B_ * S_, 256>>>(attn, h, g1, be1, h1, h1r);

    // 5) f1 = GELU(h1 @ w1 + b1)
    mma_gemm<1><<<dim3(F_ / 128, (B_ * S_) / 128, 1), 256, DYN_SMEM>>>(
        h1r, w1T, b1, f1, B_ * S_, F_, D_, 0, 0, 0, 1.0f);

    // 6) f2 = f1 @ w2 + b2
    mma_gemm<2><<<dim3(D_ / 128, (B_ * S_) / 128, 1), 256, DYN_SMEM>>>(
        f1, w2T, b2, f2, B_ * S_, D_, F_, 0, 0, 0, 1.0f);

    // 7) out = LN2(h1 + f2)
    add_ln_kernel<<<B_ * S_, 256>>>(f2, h1, g2, be2, out, nullptr);
}

// round 5
// speedup vs baseline: 3.3734x; 1.1220x over previous
#include <cuda_runtime.h>
#include <math.h>
#include <stdint.h>

#define B_ 4
#define S_ 2048
#define D_ 1024
#define F_ 4096

// ---------------- scratch (static device globals; no allocs) ----------------
__device__ float g_scores[(size_t)B_ * S_ * S_];   // 64 MB
__device__ float g_attn  [(size_t)B_ * S_ * D_];   // 32 MB
__device__ float g_h1    [(size_t)B_ * S_ * D_];   // 32 MB (fp32 residual)
__device__ float g_h1r   [(size_t)B_ * S_ * D_];   // 32 MB (tf32-rounded)
__device__ float g_f1    [(size_t)B_ * S_ * F_];   // 128 MB
__device__ float g_f2    [(size_t)B_ * S_ * D_];   // 32 MB
__device__ float g_hr    [(size_t)B_ * S_ * D_];   // 32 MB rounded h
__device__ float g_hT    [(size_t)B_ * D_ * S_];   // 32 MB h^T (rounded)
__device__ float g_w1T   [(size_t)F_ * D_];        // 16 MB
__device__ float g_w2T   [(size_t)D_ * F_];        // 16 MB

// ---------------- helpers ----------------
__device__ __forceinline__ uint32_t smem_u32(const void* p) {
    return (uint32_t)__cvta_generic_to_shared(p);
}
__device__ __forceinline__ float tf32r(float x) {  // round-to-nearest tf32
    uint32_t u;
    asm("cvt.rna.tf32.f32 %0, %1;" : "=r"(u) : "f"(x));
    return __uint_as_float(u);
}

#define CP_ASYNC16(sa, ga) \
    asm volatile("cp.async.cg.shared.global [%0], [%1], 16;" :: "r"(sa), "l"(ga))
#define CP_COMMIT() asm volatile("cp.async.commit_group;" ::: "memory")
#define CP_WAIT1()  asm volatile("cp.async.wait_group 1;" ::: "memory")

// m16n8k8 tf32 MMA (legacy path — supported on bare sm_103)
__device__ __forceinline__ void mma_tf32(float* d, const uint32_t* a, const uint32_t* b) {
    asm volatile(
        "mma.sync.aligned.m16n8k8.row.col.f32.tf32.tf32.f32 "
        "{%0,%1,%2,%3}, {%4,%5,%6,%7}, {%8,%9}, {%0,%1,%2,%3};"
        : "+f"(d[0]), "+f"(d[1]), "+f"(d[2]), "+f"(d[3])
        : "r"(a[0]), "r"(a[1]), "r"(a[2]), "r"(a[3]), "r"(b[0]), "r"(b[1]));
}

// ---------------- tf32 GEMM ----------------
// C[M,N] = A[M,K] * B_op[N,K]^T. Both operands K-major fp32, pre-rounded tf32.
// CTA tile 128x128, K-chunk 32, 3-stage cp.async ring, ONE sync per chunk,
// 2 CTAs/SM. SMEM rows padded to 36 floats (conflict-free fragment LDS).
// EPI: 0 = *alpha ; 1 = +bias, exact GELU, tf32-round ; 2 = +bias.
#define KC 32
#define LDT 36
#define TILE_BYTES (128 * LDT * 4)        // 18432
#define STAGE_BYTES (2 * TILE_BYTES)      // 36864 (A + B)
#define NSTAGE 3
#define DYN_SMEM (NSTAGE * STAGE_BYTES)   // 110592 -> 2 CTAs = 216 KB/SM

__device__ __forceinline__ void load_tile(uint32_t sbase, const float* __restrict__ Arow,
                                          const float* __restrict__ Brow,
                                          int K, int kc, int tid) {
    const int r0  = tid >> 3;           // 0..31
    const int c4  = (tid & 7) * 4;      // float offset within 32
    const int c16 = (tid & 7) * 16;     // byte offset
    const float* Ap = Arow + (size_t)kc * KC + c4;
    const float* Bp = Brow + (size_t)kc * KC + c4;
#pragma unroll
    for (int i = 0; i < 4; i++) {
        int r = r0 + i * 32;
        CP_ASYNC16(sbase + r * (LDT * 4) + c16, Ap + (size_t)r * K);
    }
    uint32_t bb = sbase + TILE_BYTES;
#pragma unroll
    for (int i = 0; i < 4; i++) {
        int r = r0 + i * 32;
        CP_ASYNC16(bb + r * (LDT * 4) + c16, Bp + (size_t)r * K);
    }
}

template <int EPI>
__global__ __launch_bounds__(256, 2)
void mma_gemm(const float* __restrict__ A, const float* __restrict__ Bm,
              const float* __restrict__ bias, float* __restrict__ C,
              int M, int N, int K, size_t sA, size_t sB, size_t sC, float alpha) {
    extern __shared__ char dsm[];
    const int tid = threadIdx.x, wid = tid >> 5, lane = tid & 31;
    const int z = blockIdx.z;
    A  += (size_t)z * sA;
    Bm += (size_t)z * sB;
    C  += (size_t)z * sC;
    const int m0 = blockIdx.y * 128;
    const int n0 = blockIdx.x * 128;
    const float* Arow = A + (size_t)m0 * K;
    const float* Brow = Bm + (size_t)n0 * K;
    const int NC = K / KC;

    // warp tile: 32(m) x 64(n); warps 4(m) x 2(n)
    const int wm = (wid & 3) * 32;
    const int wn = (wid >> 2) * 64;
    const int gq = lane >> 2;      // group id (0..7)
    const int tg = lane & 3;       // thread in group

    float acc[2][8][4];
#pragma unroll
    for (int i = 0; i < 2; i++)
#pragma unroll
        for (int j = 0; j < 8; j++)
#pragma unroll
            for (int q = 0; q < 4; q++) acc[i][j][q] = 0.0f;

    const uint32_t s0 = smem_u32(dsm);
    // prologue: stages 0,1
    load_tile(s0, Arow, Brow, K, 0, tid);
    CP_COMMIT();
    load_tile(s0 + STAGE_BYTES, Arow, Brow, K, 1, tid);
    CP_COMMIT();

    int buf = 0;
    for (int k = 0; k < NC; k++) {
        CP_WAIT1();          // chunk k resident (<=1 group outstanding)
        __syncthreads();     // single barrier: also frees buffer consumed at k-1
        if (k + 2 < NC) {
            int nb = buf + 2;
            if (nb >= NSTAGE) nb -= NSTAGE;
            load_tile(s0 + nb * STAGE_BYTES, Arow, Brow, K, k + 2, tid);
        }
        CP_COMMIT();

        const uint32_t* As = (const uint32_t*)(dsm + buf * STAGE_BYTES);
        const uint32_t* Bs = (const uint32_t*)(dsm + buf * STAGE_BYTES + TILE_BYTES);
        const uint32_t* a_lo = As + (wm + gq) * LDT + tg;
        const uint32_t* b_lo = Bs + (wn + gq) * LDT + tg;

#pragma unroll
        for (int ks = 0; ks < 4; ks++) {
            const int kb = ks * 8;
            uint32_t afr[2][4];
#pragma unroll
            for (int i = 0; i < 2; i++) {
                const uint32_t* p = a_lo + i * 16 * LDT + kb;
                afr[i][0] = p[0];
                afr[i][1] = p[8 * LDT];
                afr[i][2] = p[4];
                afr[i][3] = p[8 * LDT + 4];
            }
            uint32_t bfr[8][2];
#pragma unroll
            for (int j = 0; j < 8; j++) {
                const uint32_t* p = b_lo + j * 8 * LDT + kb;
                bfr[j][0] = p[0];
                bfr[j][1] = p[4];
            }
#pragma unroll
            for (int i = 0; i < 2; i++)
#pragma unroll
                for (int j = 0; j < 8; j++) mma_tf32(acc[i][j], afr[i], bfr[j]);
        }
        buf++;
        if (buf == NSTAGE) buf = 0;
        // no trailing __syncthreads: next iteration's barrier provides it
    }

    // epilogue: direct stores (float2 per row-pair fragment)
#pragma unroll
    for (int i = 0; i < 2; i++) {
        const int rb = m0 + wm + i * 16 + gq;
#pragma unroll
        for (int j = 0; j < 8; j++) {
            const int cb = n0 + wn + j * 8 + tg * 2;
            float bx = 0.f, by = 0.f;
            if (EPI != 0) { bx = bias[cb]; by = bias[cb + 1]; }
#pragma unroll
            for (int h = 0; h < 2; h++) {   // row, row+8
                float x = acc[i][j][h * 2 + 0];
                float y = acc[i][j][h * 2 + 1];
                if (EPI == 0) {
                    x *= alpha; y *= alpha;
                } else {
                    x += bx; y += by;
                    if (EPI == 1) {
                        x = tf32r(0.5f * x * (1.0f + erff(x * 0.7071067811865475f)));
                        y = tf32r(0.5f * y * (1.0f + erff(y * 0.7071067811865475f)));
                    }
                }
                *(float2*)(C + (size_t)(rb + h * 8) * N + cb) = make_float2(x, y);
            }
        }
    }
}

// ---------------- pointwise / reduction kernels ----------------
__device__ __forceinline__ float warpSum(float v) {
#pragma unroll
    for (int o = 16; o > 0; o >>= 1) v += __shfl_xor_sync(0xFFFFFFFFu, v, o);
    return v;
}
__device__ __forceinline__ float warpMax(float v) {
#pragma unroll
    for (int o = 16; o > 0; o >>= 1) v = fmaxf(v, __shfl_xor_sync(0xFFFFFFFFu, v, o));
    return v;
}
__device__ __forceinline__ float blockSum(float v) {
    __shared__ float sh[9];
    __syncthreads();
    int lane = threadIdx.x & 31, w = threadIdx.x >> 5;
    v = warpSum(v);
    if (lane == 0) sh[w] = v;
    __syncthreads();
    if (w == 0) {
        float x = (lane < 8) ? sh[lane] : 0.0f;
        x = warpSum(x);
        if (lane == 0) sh[8] = x;
    }
    __syncthreads();
    return sh[8];
}
__device__ __forceinline__ float blockMax(float v) {
    __shared__ float sh[9];
    __syncthreads();
    int lane = threadIdx.x & 31, w = threadIdx.x >> 5;
    v = warpMax(v);
    if (lane == 0) sh[w] = v;
    __syncthreads();
    if (w == 0) {
        float x = (lane < 8) ? sh[lane] : -INFINITY;
        x = warpMax(x);
        if (lane == 0) sh[8] = x;
    }
    __syncthreads();
    return sh[8];
}

__global__ __launch_bounds__(256)
void softmax_kernel(float* __restrict__ scores, const float* __restrict__ mask) {
    const int row = blockIdx.x;
    const int b = row / S_;
    float* p = scores + (size_t)row * S_;
    const float* mk = mask + (size_t)b * S_;
    const int t = threadIdx.x;
    float v[8];
    float mx = -INFINITY;
#pragma unroll
    for (int i = 0; i < 8; i++) {
        int k = t + i * 256;
        v[i] = p[k] + mk[k];
        mx = fmaxf(mx, v[i]);
    }
    mx = blockMax(mx);
    float s = 0.0f;
#pragma unroll
    for (int i = 0; i < 8; i++) {
        v[i] = __expf(v[i] - mx);
        s += v[i];
    }
    s = blockSum(s);
    float inv = 1.0f / s;
#pragma unroll
    for (int i = 0; i < 8; i++) p[t + i * 256] = tf32r(v[i] * inv);  // feeds tf32 GEMM
}

__global__ __launch_bounds__(256)
void add_ln_kernel(const float* __restrict__ x, const float* __restrict__ res,
                   const float* __restrict__ gamma, const float* __restrict__ beta,
                   float* __restrict__ out, float* __restrict__ out_r) {
    const int row = blockIdx.x;
    const float* px = x + (size_t)row * D_;
    const float* pr = res + (size_t)row * D_;
    float* po = out + (size_t)row * D_;
    const int t = threadIdx.x;
    float v[4];
    float s = 0.0f, s2 = 0.0f;
#pragma unroll
    for (int i = 0; i < 4; i++) {
        int k = t + i * 256;
        v[i] = px[k] + pr[k];
        s += v[i];
        s2 += v[i] * v[i];
    }
    s = blockSum(s);
    s2 = blockSum(s2);
    const float mu = s * (1.0f / D_);
    const float var = s2 * (1.0f / D_) - mu * mu;
    const float inv = rsqrtf(var + 1e-5f);
#pragma unroll
    for (int i = 0; i < 4; i++) {
        int k = t + i * 256;
        float y = (v[i] - mu) * inv * gamma[k] + beta[k];
        po[k] = y;
        if (out_r) out_r[(size_t)row * D_ + k] = tf32r(y);
    }
}

// dst[c,r] = round_tf32(src[r,c]); batched by z with strides.
__global__ __launch_bounds__(256)
void transpose_kernel(const float* __restrict__ src, float* __restrict__ dst,
                      int R, int C, size_t sS, size_t sD) {
    __shared__ float t[32][33];
    src += (size_t)blockIdx.z * sS;
    dst += (size_t)blockIdx.z * sD;
    const int c0 = blockIdx.x * 32, r0 = blockIdx.y * 32;
    const int x = threadIdx.x & 31, y = (threadIdx.x >> 5) * 4;
#pragma unroll
    for (int i = 0; i < 4; i++)
        t[y + i][x] = src[(size_t)(r0 + y + i) * C + c0 + x];
    __syncthreads();
#pragma unroll
    for (int i = 0; i < 4; i++)
        dst[(size_t)(c0 + y + i) * R + r0 + x] = tf32r(t[x][y + i]);
}

__global__ __launch_bounds__(256)
void round_copy_kernel(const float* __restrict__ src, float* __restrict__ dst, size_t n4) {
    size_t i = (size_t)blockIdx.x * 256 + threadIdx.x;
    if (i < n4) {
        float4 v = ((const float4*)src)[i];
        v.x = tf32r(v.x); v.y = tf32r(v.y); v.z = tf32r(v.z); v.w = tf32r(v.w);
        ((float4*)dst)[i] = v;
    }
}

// ---------------- launch ----------------
extern "C" void kernel_launch(void* const* d_in, const int* in_sizes, int n_in,
                              void* d_out, int out_size) {
    const float* h    = (const float*)d_in[0];
    const float* mask = (const float*)d_in[1];
    const float* w1   = (const float*)d_in[2];
    const float* b1   = (const float*)d_in[3];
    const float* w2   = (const float*)d_in[4];
    const float* b2   = (const float*)d_in[5];
    const float* g1   = (const float*)d_in[6];
    const float* be1  = (const float*)d_in[7];
    const float* g2   = (const float*)d_in[8];
    const float* be2  = (const float*)d_in[9];
    float* out = (float*)d_out;

    float *scores, *attn, *h1, *h1r, *f1, *f2, *hr, *hT, *w1T, *w2T;
    cudaGetSymbolAddress((void**)&scores, g_scores);
    cudaGetSymbolAddress((void**)&attn, g_attn);
    cudaGetSymbolAddress((void**)&h1, g_h1);
    cudaGetSymbolAddress((void**)&h1r, g_h1r);
    cudaGetSymbolAddress((void**)&f1, g_f1);
    cudaGetSymbolAddress((void**)&f2, g_f2);
    cudaGetSymbolAddress((void**)&hr, g_hr);
    cudaGetSymbolAddress((void**)&hT, g_hT);
    cudaGetSymbolAddress((void**)&w1T, g_w1T);
    cudaGetSymbolAddress((void**)&w2T, g_w2T);

    cudaFuncSetAttribute(mma_gemm<0>, cudaFuncAttributeMaxDynamicSharedMemorySize, DYN_SMEM);
    cudaFuncSetAttribute(mma_gemm<1>, cudaFuncAttributeMaxDynamicSharedMemorySize, DYN_SMEM);
    cudaFuncSetAttribute(mma_gemm<2>, cudaFuncAttributeMaxDynamicSharedMemorySize, DYN_SMEM);

    const size_t SD = (size_t)S_ * D_;
    const size_t SS = (size_t)S_ * S_;

    // operand prep: tf32 rounding + K-major transposes
    round_copy_kernel<<<(B_ * SD / 4 + 255) / 256, 256>>>(h, hr, B_ * SD / 4);
    transpose_kernel<<<dim3(D_ / 32, S_ / 32, B_), 256>>>(h, hT, S_, D_, SD, SD);
    transpose_kernel<<<dim3(F_ / 32, D_ / 32, 1), 256>>>(w1, w1T, D_, F_, 0, 0);
    transpose_kernel<<<dim3(D_ / 32, F_ / 32, 1), 256>>>(w2, w2T, F_, D_, 0, 0);

    // 1) scores = (h @ h^T) / 32
    mma_gemm<0><<<dim3(S_ / 128, S_ / 128, B_), 256, DYN_SMEM>>>(
        hr, hr, nullptr, scores, S_, S_, D_, SD, SD, SS, 0.03125f);

    // 2) softmax (+mask), tf32-rounded
    softmax_kernel<<<B_ * S_, 256>>>(scores, mask);

    // 3) attn = P @ h   (B_op = h^T, K-major)
    mma_gemm<0><<<dim3(D_ / 128, S_ / 128, B_), 256, DYN_SMEM>>>(
        scores, hT, nullptr, attn, S_, D_, S_, SS, SD, SD, 1.0f);

    // 4) h1 = LN1(h + attn)  (+ rounded twin)
    add_ln_kernel<<<B_ * S_, 256>>>(attn, h, g1, be1, h1, h1r);

    // 5) f1 = GELU(h1 @ w1 + b1)
    mma_gemm<1><<<dim3(F_ / 128, (B_ * S_) / 128, 1), 256, DYN_SMEM>>>(
        h1r, w1T, b1, f1, B_ * S_, F_, D_, 0, 0, 0, 1.0f);

    // 6) f2 = f1 @ w2 + b2
    mma_gemm<2><<<dim3(D_ / 128, (B_ * S_) / 128, 1), 256, DYN_SMEM>>>(
        f1, w2T, b2, f2, B_ * S_, D_, F_, 0, 0, 0, 1.0f);

    // 7) out = LN2(h1 + f2)
    add_ln_kernel<<<B_ * S_, 256>>>(f2, h1, g2, be2, out, nullptr);
}

// round 6
// speedup vs baseline: 3.3784x; 1.0015x over previous
#include <cuda_runtime.h>
#include <math.h>
#include <stdint.h>

#define B_ 4
#define S_ 2048
#define D_ 1024
#define F_ 4096

// ---------------- scratch (static device globals; no allocs) ----------------
__device__ float g_scores[(size_t)B_ * S_ * S_];   // 64 MB
__device__ float g_attn  [(size_t)B_ * S_ * D_];   // 32 MB
__device__ float g_h1    [(size_t)B_ * S_ * D_];   // 32 MB (fp32 residual)
__device__ float g_h1r   [(size_t)B_ * S_ * D_];   // 32 MB (tf32-rounded)
__device__ float g_f1    [(size_t)B_ * S_ * F_];   // 128 MB
__device__ float g_f2    [(size_t)B_ * S_ * D_];   // 32 MB
__device__ float g_hr    [(size_t)B_ * S_ * D_];   // 32 MB rounded h
__device__ float g_hT    [(size_t)B_ * D_ * S_];   // 32 MB h^T (rounded)
__device__ float g_w1T   [(size_t)F_ * D_];        // 16 MB
__device__ float g_w2T   [(size_t)D_ * F_];        // 16 MB

// ---------------- helpers ----------------
__device__ __forceinline__ uint32_t smem_u32(const void* p) {
    return (uint32_t)__cvta_generic_to_shared(p);
}
__device__ __forceinline__ float tf32r(float x) {  // round-to-nearest tf32
    uint32_t u;
    asm("cvt.rna.tf32.f32 %0, %1;" : "=r"(u) : "f"(x));
    return __uint_as_float(u);
}

#define CP_ASYNC16(sa, ga) \
    asm volatile("cp.async.cg.shared.global [%0], [%1], 16;" :: "r"(sa), "l"(ga))
#define CP_COMMIT() asm volatile("cp.async.commit_group;" ::: "memory")
#define CP_WAIT1()  asm volatile("cp.async.wait_group 1;" ::: "memory")

// m16n8k8 tf32 MMA (legacy path — supported on bare sm_103)
__device__ __forceinline__ void mma_tf32(float* d, const uint32_t* a, const uint32_t* b) {
    asm volatile(
        "mma.sync.aligned.m16n8k8.row.col.f32.tf32.tf32.f32 "
        "{%0,%1,%2,%3}, {%4,%5,%6,%7}, {%8,%9}, {%0,%1,%2,%3};"
        : "+f"(d[0]), "+f"(d[1]), "+f"(d[2]), "+f"(d[3])
        : "r"(a[0]), "r"(a[1]), "r"(a[2]), "r"(a[3]), "r"(b[0]), "r"(b[1]));
}

// ---------------- tf32 GEMM ----------------
// C[M,N] = A[M,K] * B_op[N,K]^T. Both operands K-major fp32, pre-rounded tf32.
// CTA tile 128(M) x 256(N), warp tile 64x64 (8 warps, 2m x 4n), K-chunk 32,
// 3-stage cp.async ring, one barrier per chunk. Rows padded to 36 floats.
// EPI: 0 = *alpha ; 1 = +bias, exact GELU, tf32-round ; 2 = +bias.
#define KC 32
#define LDT 36
#define A_TILE_BYTES (128 * LDT * 4)              // 18432
#define B_TILE_BYTES (256 * LDT * 4)              // 36864
#define STAGE_BYTES (A_TILE_BYTES + B_TILE_BYTES) // 55296
#define NSTAGE 3
#define DYN_SMEM (NSTAGE * STAGE_BYTES)           // 165888 (1 CTA/SM)

__device__ __forceinline__ void load_tile(uint32_t sbase, const float* __restrict__ Arow,
                                          const float* __restrict__ Brow,
                                          int K, int kc, int tid) {
    const int r0  = tid >> 3;           // 0..31
    const int c4  = (tid & 7) * 4;      // float offset within 32
    const int c16 = (tid & 7) * 16;     // byte offset
    const float* Ap = Arow + (size_t)kc * KC + c4;
    const float* Bp = Brow + (size_t)kc * KC + c4;
#pragma unroll
    for (int i = 0; i < 4; i++) {       // A: 128 rows
        int r = r0 + i * 32;
        CP_ASYNC16(sbase + r * (LDT * 4) + c16, Ap + (size_t)r * K);
    }
    uint32_t bb = sbase + A_TILE_BYTES;
#pragma unroll
    for (int i = 0; i < 8; i++) {       // B: 256 rows
        int r = r0 + i * 32;
        CP_ASYNC16(bb + r * (LDT * 4) + c16, Bp + (size_t)r * K);
    }
}

template <int EPI>
__global__ __launch_bounds__(256, 1)
void mma_gemm(const float* __restrict__ A, const float* __restrict__ Bm,
              const float* __restrict__ bias, float* __restrict__ C,
              int M, int N, int K, size_t sA, size_t sB, size_t sC, float alpha) {
    extern __shared__ char dsm[];
    const int tid = threadIdx.x, wid = tid >> 5, lane = tid & 31;
    const int z = blockIdx.z;
    A  += (size_t)z * sA;
    Bm += (size_t)z * sB;
    C  += (size_t)z * sC;
    const int m0 = blockIdx.y * 128;
    const int n0 = blockIdx.x * 256;
    const float* Arow = A + (size_t)m0 * K;
    const float* Brow = Bm + (size_t)n0 * K;
    const int NC = K / KC;

    // warp tile: 64(m) x 64(n); warps 2(m) x 4(n)
    const int wm = (wid & 1) * 64;
    const int wn = (wid >> 1) * 64;
    const int gq = lane >> 2;      // group id (0..7)
    const int tg = lane & 3;       // thread in group

    float acc[4][8][4];            // 4 m16-groups x 8 n8-tiles x 4
#pragma unroll
    for (int g = 0; g < 4; g++)
#pragma unroll
        for (int j = 0; j < 8; j++)
#pragma unroll
            for (int q = 0; q < 4; q++) acc[g][j][q] = 0.0f;

    const uint32_t s0 = smem_u32(dsm);
    load_tile(s0, Arow, Brow, K, 0, tid);
    CP_COMMIT();
    load_tile(s0 + STAGE_BYTES, Arow, Brow, K, 1, tid);
    CP_COMMIT();

    int buf = 0;
    for (int k = 0; k < NC; k++) {
        CP_WAIT1();          // chunk k resident
        __syncthreads();     // single barrier; also frees buffer consumed at k-1
        if (k + 2 < NC) {
            int nb = buf + 2;
            if (nb >= NSTAGE) nb -= NSTAGE;
            load_tile(s0 + nb * STAGE_BYTES, Arow, Brow, K, k + 2, tid);
        }
        CP_COMMIT();

        const uint32_t* As = (const uint32_t*)(dsm + buf * STAGE_BYTES);
        const uint32_t* Bs = (const uint32_t*)(dsm + buf * STAGE_BYTES + A_TILE_BYTES);
        const uint32_t* a_lo = As + (wm + gq) * LDT + tg;   // + g*16*LDT
        const uint32_t* b_lo = Bs + (wn + gq) * LDT + tg;   // + j*8*LDT

#pragma unroll
        for (int ks = 0; ks < 4; ks++) {
            const int kb = ks * 8;
            uint32_t afr[4][4];
#pragma unroll
            for (int g = 0; g < 4; g++) {
                const uint32_t* p = a_lo + g * 16 * LDT + kb;
                afr[g][0] = p[0];
                afr[g][1] = p[8 * LDT];
                afr[g][2] = p[4];
                afr[g][3] = p[8 * LDT + 4];
            }
            uint32_t bfr[8][2];
#pragma unroll
            for (int j = 0; j < 8; j++) {
                const uint32_t* p = b_lo + j * 8 * LDT + kb;
                bfr[j][0] = p[0];
                bfr[j][1] = p[4];
            }
#pragma unroll
            for (int g = 0; g < 4; g++)
#pragma unroll
                for (int j = 0; j < 8; j++) mma_tf32(acc[g][j], afr[g], bfr[j]);
        }
        buf++;
        if (buf == NSTAGE) buf = 0;
    }

    // epilogue: direct stores (float2 per row-pair fragment)
#pragma unroll
    for (int g = 0; g < 4; g++) {
        const int rb = m0 + wm + g * 16 + gq;
#pragma unroll
        for (int j = 0; j < 8; j++) {
            const int cb = n0 + wn + j * 8 + tg * 2;
            float bx = 0.f, by = 0.f;
            if (EPI != 0) { bx = bias[cb]; by = bias[cb + 1]; }
#pragma unroll
            for (int hh = 0; hh < 2; hh++) {   // row, row+8
                float x = acc[g][j][hh * 2 + 0];
                float y = acc[g][j][hh * 2 + 1];
                if (EPI == 0) {
                    x *= alpha; y *= alpha;
                } else {
                    x += bx; y += by;
                    if (EPI == 1) {
                        x = tf32r(0.5f * x * (1.0f + erff(x * 0.7071067811865475f)));
                        y = tf32r(0.5f * y * (1.0f + erff(y * 0.7071067811865475f)));
                    }
                }
                *(float2*)(C + (size_t)(rb + hh * 8) * N + cb) = make_float2(x, y);
            }
        }
    }
}

// ---------------- pointwise / reduction kernels ----------------
__device__ __forceinline__ float warpSum(float v) {
#pragma unroll
    for (int o = 16; o > 0; o >>= 1) v += __shfl_xor_sync(0xFFFFFFFFu, v, o);
    return v;
}
__device__ __forceinline__ float warpMax(float v) {
#pragma unroll
    for (int o = 16; o > 0; o >>= 1) v = fmaxf(v, __shfl_xor_sync(0xFFFFFFFFu, v, o));
    return v;
}
__device__ __forceinline__ float blockSum(float v) {
    __shared__ float sh[9];
    __syncthreads();
    int lane = threadIdx.x & 31, w = threadIdx.x >> 5;
    v = warpSum(v);
    if (lane == 0) sh[w] = v;
    __syncthreads();
    if (w == 0) {
        float x = (lane < 8) ? sh[lane] : 0.0f;
        x = warpSum(x);
        if (lane == 0) sh[8] = x;
    }
    __syncthreads();
    return sh[8];
}
__device__ __forceinline__ float blockMax(float v) {
    __shared__ float sh[9];
    __syncthreads();
    int lane = threadIdx.x & 31, w = threadIdx.x >> 5;
    v = warpMax(v);
    if (lane == 0) sh[w] = v;
    __syncthreads();
    if (w == 0) {
        float x = (lane < 8) ? sh[lane] : -INFINITY;
        x = warpMax(x);
        if (lane == 0) sh[8] = x;
    }
    __syncthreads();
    return sh[8];
}

__global__ __launch_bounds__(256)
void softmax_kernel(float* __restrict__ scores, const float* __restrict__ mask) {
    const int row = blockIdx.x;
    const int b = row / S_;
    float* p = scores + (size_t)row * S_;
    const float* mk = mask + (size_t)b * S_;
    const int t = threadIdx.x;
    float v[8];
    float mx = -INFINITY;
#pragma unroll
    for (int i = 0; i < 8; i++) {
        int k = t + i * 256;
        v[i] = p[k] + mk[k];
        mx = fmaxf(mx, v[i]);
    }
    mx = blockMax(mx);
    float s = 0.0f;
#pragma unroll
    for (int i = 0; i < 8; i++) {
        v[i] = __expf(v[i] - mx);
        s += v[i];
    }
    s = blockSum(s);
    float inv = 1.0f / s;
#pragma unroll
    for (int i = 0; i < 8; i++) p[t + i * 256] = tf32r(v[i] * inv);  // feeds tf32 GEMM
}

__global__ __launch_bounds__(256)
void add_ln_kernel(const float* __restrict__ x, const float* __restrict__ res,
                   const float* __restrict__ gamma, const float* __restrict__ beta,
                   float* __restrict__ out, float* __restrict__ out_r) {
    const int row = blockIdx.x;
    const float* px = x + (size_t)row * D_;
    const float* pr = res + (size_t)row * D_;
    float* po = out + (size_t)row * D_;
    const int t = threadIdx.x;
    float v[4];
    float s = 0.0f, s2 = 0.0f;
#pragma unroll
    for (int i = 0; i < 4; i++) {
        int k = t + i * 256;
        v[i] = px[k] + pr[k];
        s += v[i];
        s2 += v[i] * v[i];
    }
    s = blockSum(s);
    s2 = blockSum(s2);
    const float mu = s * (1.0f / D_);
    const float var = s2 * (1.0f / D_) - mu * mu;
    const float inv = rsqrtf(var + 1e-5f);
#pragma unroll
    for (int i = 0; i < 4; i++) {
        int k = t + i * 256;
        float y = (v[i] - mu) * inv * gamma[k] + beta[k];
        po[k] = y;
        if (out_r) out_r[(size_t)row * D_ + k] = tf32r(y);
    }
}

// dst[c,r] = round_tf32(src[r,c]); batched by z with strides.
__global__ __launch_bounds__(256)
void transpose_kernel(const float* __restrict__ src, float* __restrict__ dst,
                      int R, int C, size_t sS, size_t sD) {
    __shared__ float t[32][33];
    src += (size_t)blockIdx.z * sS;
    dst += (size_t)blockIdx.z * sD;
    const int c0 = blockIdx.x * 32, r0 = blockIdx.y * 32;
    const int x = threadIdx.x & 31, y = (threadIdx.x >> 5) * 4;
#pragma unroll
    for (int i = 0; i < 4; i++)
        t[y + i][x] = src[(size_t)(r0 + y + i) * C + c0 + x];
    __syncthreads();
#pragma unroll
    for (int i = 0; i < 4; i++)
        dst[(size_t)(c0 + y + i) * R + r0 + x] = tf32r(t[x][y + i]);
}

__global__ __launch_bounds__(256)
void round_copy_kernel(const float* __restrict__ src, float* __restrict__ dst, size_t n4) {
    size_t i = (size_t)blockIdx.x * 256 + threadIdx.x;
    if (i < n4) {
        float4 v = ((const float4*)src)[i];
        v.x = tf32r(v.x); v.y = tf32r(v.y); v.z = tf32r(v.z); v.w = tf32r(v.w);
        ((float4*)dst)[i] = v;
    }
}

// ---------------- launch ----------------
extern "C" void kernel_launch(void* const* d_in, const int* in_sizes, int n_in,
                              void* d_out, int out_size) {
    const float* h    = (const float*)d_in[0];
    const float* mask = (const float*)d_in[1];
    const float* w1   = (const float*)d_in[2];
    const float* b1   = (const float*)d_in[3];
    const float* w2   = (const float*)d_in[4];
    const float* b2   = (const float*)d_in[5];
    const float* g1   = (const float*)d_in[6];
    const float* be1  = (const float*)d_in[7];
    const float* g2   = (const float*)d_in[8];
    const float* be2  = (const float*)d_in[9];
    float* out = (float*)d_out;

    float *scores, *attn, *h1, *h1r, *f1, *f2, *hr, *hT, *w1T, *w2T;
    cudaGetSymbolAddress((void**)&scores, g_scores);
    cudaGetSymbolAddress((void**)&attn, g_attn);
    cudaGetSymbolAddress((void**)&h1, g_h1);
    cudaGetSymbolAddress((void**)&h1r, g_h1r);
    cudaGetSymbolAddress((void**)&f1, g_f1);
    cudaGetSymbolAddress((void**)&f2, g_f2);
    cudaGetSymbolAddress((void**)&hr, g_hr);
    cudaGetSymbolAddress((void**)&hT, g_hT);
    cudaGetSymbolAddress((void**)&w1T, g_w1T);
    cudaGetSymbolAddress((void**)&w2T, g_w2T);

    cudaFuncSetAttribute(mma_gemm<0>, cudaFuncAttributeMaxDynamicSharedMemorySize, DYN_SMEM);
    cudaFuncSetAttribute(mma_gemm<1>, cudaFuncAttributeMaxDynamicSharedMemorySize, DYN_SMEM);
    cudaFuncSetAttribute(mma_gemm<2>, cudaFuncAttributeMaxDynamicSharedMemorySize, DYN_SMEM);

    const size_t SD = (size_t)S_ * D_;
    const size_t SS = (size_t)S_ * S_;

    // operand prep: tf32 rounding + K-major transposes
    round_copy_kernel<<<(B_ * SD / 4 + 255) / 256, 256>>>(h, hr, B_ * SD / 4);
    transpose_kernel<<<dim3(D_ / 32, S_ / 32, B_), 256>>>(h, hT, S_, D_, SD, SD);
    transpose_kernel<<<dim3(F_ / 32, D_ / 32, 1), 256>>>(w1, w1T, D_, F_, 0, 0);
    transpose_kernel<<<dim3(D_ / 32, F_ / 32, 1), 256>>>(w2, w2T, F_, D_, 0, 0);

    // 1) scores = (h @ h^T) / 32
    mma_gemm<0><<<dim3(S_ / 256, S_ / 128, B_), 256, DYN_SMEM>>>(
        hr, hr, nullptr, scores, S_, S_, D_, SD, SD, SS, 0.03125f);

    // 2) softmax (+mask), tf32-rounded
    softmax_kernel<<<B_ * S_, 256>>>(scores, mask);

    // 3) attn = P @ h   (B_op = h^T, K-major)
    mma_gemm<0><<<dim3(D_ / 256, S_ / 128, B_), 256, DYN_SMEM>>>(
        scores, hT, nullptr, attn, S_, D_, S_, SS, SD, SD, 1.0f);

    // 4) h1 = LN1(h + attn)  (+ rounded twin)
    add_ln_kernel<<<B_ * S_, 256>>>(attn, h, g1, be1, h1, h1r);

    // 5) f1 = GELU(h1 @ w1 + b1)
    mma_gemm<1><<<dim3(F_ / 256, (B_ * S_) / 128, 1), 256, DYN_SMEM>>>(
        h1r, w1T, b1, f1, B_ * S_, F_, D_, 0, 0, 0, 1.0f);

    // 6) f2 = f1 @ w2 + b2
    mma_gemm<2><<<dim3(D_ / 256, (B_ * S_) / 128, 1), 256, DYN_SMEM>>>(
        f1, w2T, b2, f2, B_ * S_, D_, F_, 0, 0, 0, 1.0f);

    // 7) out = LN2(h1 + f2)
    add_ln_kernel<<<B_ * S_, 256>>>(f2, h1, g2, be2, out, nullptr);
}

// round 7
// speedup vs baseline: 5.4778x; 1.6214x over previous
#include <cuda_runtime.h>
#include <cuda_fp16.h>
#include <math.h>
#include <stdint.h>

#define B_ 4
#define S_ 2048
#define D_ 1024
#define F_ 4096

// ---------------- scratch (static device globals; no allocs) ----------------
__device__ float  g_scores[(size_t)B_ * S_ * S_];   // 64 MB fp32
__device__ __half g_probs [(size_t)B_ * S_ * S_];   // 32 MB fp16
__device__ float  g_attn  [(size_t)B_ * S_ * D_];   // 32 MB
__device__ float  g_h1    [(size_t)B_ * S_ * D_];   // 32 MB fp32 residual
__device__ __half g_h1h   [(size_t)B_ * S_ * D_];   // 16 MB fp16 twin
__device__ __half g_f1    [(size_t)B_ * S_ * F_];   // 64 MB fp16
__device__ float  g_f2    [(size_t)B_ * S_ * D_];   // 32 MB
__device__ __half g_hh    [(size_t)B_ * S_ * D_];   // 16 MB h as fp16
__device__ __half g_hT    [(size_t)B_ * D_ * S_];   // 16 MB h^T fp16
__device__ __half g_w1T   [(size_t)F_ * D_];        // 8 MB
__device__ __half g_w2T   [(size_t)D_ * F_];        // 8 MB

// ---------------- helpers ----------------
__device__ __forceinline__ uint32_t smem_u32(const void* p) {
    return (uint32_t)__cvta_generic_to_shared(p);
}

#define CP_ASYNC16(sa, ga) \
    asm volatile("cp.async.cg.shared.global [%0], [%1], 16;" :: "r"(sa), "l"(ga))
#define CP_COMMIT() asm volatile("cp.async.commit_group;" ::: "memory")
#define CP_WAIT2()  asm volatile("cp.async.wait_group 2;" ::: "memory")

// fp16 m16n8k16 MMA, fp32 accumulate (legacy path — supported on bare sm_103)
__device__ __forceinline__ void mma_f16(float* d, const uint32_t* a, const uint32_t* b) {
    asm volatile(
        "mma.sync.aligned.m16n8k16.row.col.f32.f16.f16.f32 "
        "{%0,%1,%2,%3}, {%4,%5,%6,%7}, {%8,%9}, {%0,%1,%2,%3};"
        : "+f"(d[0]), "+f"(d[1]), "+f"(d[2]), "+f"(d[3])
        : "r"(a[0]), "r"(a[1]), "r"(a[2]), "r"(a[3]), "r"(b[0]), "r"(b[1]));
}

// ---------------- fp16 GEMM ----------------
// C[M,N] = A[M,K] * B_op[N,K]^T. Operands fp16 K-major. fp32 accumulation.
// CTA tile 128x128, warp tile 32x64 (8 warps 4m x 2n), K-chunk 32 halfs,
// 4-stage cp.async ring, one barrier per chunk, 2 CTAs/SM.
// SMEM row = 32 halfs (64B), pitch 80B (20 u32) -> conflict-free fragments.
// EPI: 0 = *alpha (float out) ; 1 = +bias, exact GELU (half out) ; 2 = +bias (float out).
#define KC 32
#define PITCH 20                              // u32 per row
#define ROW_BYTES 80
#define T_TILE_BYTES (128 * ROW_BYTES)        // 10240
#define STAGE_BYTES (2 * T_TILE_BYTES)        // 20480 (A + B)
#define NSTAGE 4
#define DYN_SMEM (NSTAGE * STAGE_BYTES)       // 81920 -> 2 CTAs = 160 KB/SM

__device__ __forceinline__ void load_tile(uint32_t sbase, const __half* __restrict__ Arow,
                                          const __half* __restrict__ Brow,
                                          int K, int kc, int tid) {
    const int r0 = tid >> 2;            // 0..63
    const int c  = tid & 3;             // 16B chunk (8 halfs)
    const __half* Ap = Arow + (size_t)kc * KC + c * 8;
    const __half* Bp = Brow + (size_t)kc * KC + c * 8;
#pragma unroll
    for (int i = 0; i < 2; i++) {
        int r = r0 + i * 64;
        CP_ASYNC16(sbase + r * ROW_BYTES + c * 16, Ap + (size_t)r * K);
    }
    uint32_t bb = sbase + T_TILE_BYTES;
#pragma unroll
    for (int i = 0; i < 2; i++) {
        int r = r0 + i * 64;
        CP_ASYNC16(bb + r * ROW_BYTES + c * 16, Bp + (size_t)r * K);
    }
}

template <int EPI, typename OutT>
__global__ __launch_bounds__(256, 2)
void mma_gemm(const __half* __restrict__ A, const __half* __restrict__ Bm,
              const float* __restrict__ bias, OutT* __restrict__ C,
              int M, int N, int K, size_t sA, size_t sB, size_t sC, float alpha) {
    extern __shared__ char dsm[];
    const int tid = threadIdx.x, wid = tid >> 5, lane = tid & 31;
    const int z = blockIdx.z;
    A  += (size_t)z * sA;
    Bm += (size_t)z * sB;
    C  += (size_t)z * sC;
    const int m0 = blockIdx.y * 128;
    const int n0 = blockIdx.x * 128;
    const __half* Arow = A + (size_t)m0 * K;
    const __half* Brow = Bm + (size_t)n0 * K;
    const int NC = K / KC;

    // warp tile: 32(m) x 64(n); warps 4(m) x 2(n)
    const int wm = (wid & 3) * 32;
    const int wn = (wid >> 2) * 64;
    const int gq = lane >> 2;
    const int tg = lane & 3;

    float acc[2][8][4];
#pragma unroll
    for (int i = 0; i < 2; i++)
#pragma unroll
        for (int j = 0; j < 8; j++)
#pragma unroll
            for (int q = 0; q < 4; q++) acc[i][j][q] = 0.0f;

    const uint32_t s0 = smem_u32(dsm);
    // prologue: stages 0..2
#pragma unroll
    for (int s = 0; s < NSTAGE - 1; s++) {
        load_tile(s0 + s * STAGE_BYTES, Arow, Brow, K, s, tid);
        CP_COMMIT();
    }

    for (int k = 0; k < NC; k++) {
        const int buf = k & (NSTAGE - 1);
        CP_WAIT2();          // chunk k resident (<=2 groups pending)
        __syncthreads();     // single barrier; also frees buffer consumed at k-1
        if (k + NSTAGE - 1 < NC)
            load_tile(s0 + ((k + NSTAGE - 1) & (NSTAGE - 1)) * STAGE_BYTES,
                      Arow, Brow, K, k + NSTAGE - 1, tid);
        CP_COMMIT();

        const uint32_t* As = (const uint32_t*)(dsm + buf * STAGE_BYTES);
        const uint32_t* Bs = (const uint32_t*)(dsm + buf * STAGE_BYTES + T_TILE_BYTES);
        const uint32_t* a_lo = As + (wm + gq) * PITCH + tg;
        const uint32_t* b_lo = Bs + (wn + gq) * PITCH + tg;

#pragma unroll
        for (int ks = 0; ks < 2; ks++) {      // two k16 steps per 32-half chunk
            const int kb = ks * 8;            // 16 halfs = 8 u32
            uint32_t afr[2][4];
#pragma unroll
            for (int i = 0; i < 2; i++) {
                const uint32_t* p = a_lo + i * 16 * PITCH + kb;
                afr[i][0] = p[0];             // (row gq,   k0..1)
                afr[i][1] = p[8 * PITCH];     // (row gq+8, k0..1)
                afr[i][2] = p[4];             // (row gq,   k8..9)
                afr[i][3] = p[8 * PITCH + 4]; // (row gq+8, k8..9)
            }
            uint32_t bfr[8][2];
#pragma unroll
            for (int j = 0; j < 8; j++) {
                const uint32_t* p = b_lo + j * 8 * PITCH + kb;
                bfr[j][0] = p[0];
                bfr[j][1] = p[4];
            }
#pragma unroll
            for (int i = 0; i < 2; i++)
#pragma unroll
                for (int j = 0; j < 8; j++) mma_f16(acc[i][j], afr[i], bfr[j]);
        }
    }

    // epilogue
#pragma unroll
    for (int i = 0; i < 2; i++) {
        const int rb = m0 + wm + i * 16 + gq;
#pragma unroll
        for (int j = 0; j < 8; j++) {
            const int cb = n0 + wn + j * 8 + tg * 2;
            float bx = 0.f, by = 0.f;
            if (EPI != 0) { bx = bias[cb]; by = bias[cb + 1]; }
#pragma unroll
            for (int hh = 0; hh < 2; hh++) {   // rows gq, gq+8
                float x = acc[i][j][hh * 2 + 0];
                float y = acc[i][j][hh * 2 + 1];
                if (EPI == 0) {
                    x *= alpha; y *= alpha;
                } else {
                    x += bx; y += by;
                    if (EPI == 1) {
                        x = 0.5f * x * (1.0f + erff(x * 0.7071067811865475f));
                        y = 0.5f * y * (1.0f + erff(y * 0.7071067811865475f));
                    }
                }
                OutT* cp = C + (size_t)(rb + hh * 8) * N + cb;
                if (sizeof(OutT) == 2) {
                    __half2 hv = __floats2half2_rn(x, y);
                    *(__half2*)cp = hv;
                } else {
                    *(float2*)cp = make_float2(x, y);
                }
            }
        }
    }
}

// ---------------- pointwise / reduction kernels ----------------
__device__ __forceinline__ float warpSum(float v) {
#pragma unroll
    for (int o = 16; o > 0; o >>= 1) v += __shfl_xor_sync(0xFFFFFFFFu, v, o);
    return v;
}
__device__ __forceinline__ float warpMax(float v) {
#pragma unroll
    for (int o = 16; o > 0; o >>= 1) v = fmaxf(v, __shfl_xor_sync(0xFFFFFFFFu, v, o));
    return v;
}
__device__ __forceinline__ float blockSum(float v) {
    __shared__ float sh[9];
    __syncthreads();
    int lane = threadIdx.x & 31, w = threadIdx.x >> 5;
    v = warpSum(v);
    if (lane == 0) sh[w] = v;
    __syncthreads();
    if (w == 0) {
        float x = (lane < 8) ? sh[lane] : 0.0f;
        x = warpSum(x);
        if (lane == 0) sh[8] = x;
    }
    __syncthreads();
    return sh[8];
}
__device__ __forceinline__ float blockMax(float v) {
    __shared__ float sh[9];
    __syncthreads();
    int lane = threadIdx.x & 31, w = threadIdx.x >> 5;
    v = warpMax(v);
    if (lane == 0) sh[w] = v;
    __syncthreads();
    if (w == 0) {
        float x = (lane < 8) ? sh[lane] : -INFINITY;
        x = warpMax(x);
        if (lane == 0) sh[8] = x;
    }
    __syncthreads();
    return sh[8];
}

__global__ __launch_bounds__(256)
void softmax_kernel(const float* __restrict__ scores, const float* __restrict__ mask,
                    __half* __restrict__ probs) {
    const int row = blockIdx.x;
    const int b = row / S_;
    const float* p = scores + (size_t)row * S_;
    __half* po = probs + (size_t)row * S_;
    const float* mk = mask + (size_t)b * S_;
    const int t = threadIdx.x;
    float v[8];
    float mx = -INFINITY;
#pragma unroll
    for (int i = 0; i < 8; i++) {
        int k = t + i * 256;
        v[i] = p[k] + mk[k];
        mx = fmaxf(mx, v[i]);
    }
    mx = blockMax(mx);
    float s = 0.0f;
#pragma unroll
    for (int i = 0; i < 8; i++) {
        v[i] = __expf(v[i] - mx);
        s += v[i];
    }
    s = blockSum(s);
    float inv = 1.0f / s;
#pragma unroll
    for (int i = 0; i < 8; i++) po[t + i * 256] = __float2half_rn(v[i] * inv);
}

__global__ __launch_bounds__(256)
void add_ln_kernel(const float* __restrict__ x, const float* __restrict__ res,
                   const float* __restrict__ gamma, const float* __restrict__ beta,
                   float* __restrict__ out, __half* __restrict__ out_h) {
    const int row = blockIdx.x;
    const float* px = x + (size_t)row * D_;
    const float* pr = res + (size_t)row * D_;
    float* po = out + (size_t)row * D_;
    const int t = threadIdx.x;
    float v[4];
    float s = 0.0f, s2 = 0.0f;
#pragma unroll
    for (int i = 0; i < 4; i++) {
        int k = t + i * 256;
        v[i] = px[k] + pr[k];
        s += v[i];
        s2 += v[i] * v[i];
    }
    s = blockSum(s);
    s2 = blockSum(s2);
    const float mu = s * (1.0f / D_);
    const float var = s2 * (1.0f / D_) - mu * mu;
    const float inv = rsqrtf(var + 1e-5f);
#pragma unroll
    for (int i = 0; i < 4; i++) {
        int k = t + i * 256;
        float y = (v[i] - mu) * inv * gamma[k] + beta[k];
        po[k] = y;
        if (out_h) out_h[(size_t)row * D_ + k] = __float2half_rn(y);
    }
}

// dst[c,r] = half(src[r,c]); batched by z with strides.
__global__ __launch_bounds__(256)
void transpose_h_kernel(const float* __restrict__ src, __half* __restrict__ dst,
                        int R, int C, size_t sS, size_t sD) {
    __shared__ float t[32][33];
    src += (size_t)blockIdx.z * sS;
    dst += (size_t)blockIdx.z * sD;
    const int c0 = blockIdx.x * 32, r0 = blockIdx.y * 32;
    const int x = threadIdx.x & 31, y = (threadIdx.x >> 5) * 4;
#pragma unroll
    for (int i = 0; i < 4; i++)
        t[y + i][x] = src[(size_t)(r0 + y + i) * C + c0 + x];
    __syncthreads();
#pragma unroll
    for (int i = 0; i < 4; i++)
        dst[(size_t)(c0 + y + i) * R + r0 + x] = __float2half_rn(t[x][y + i]);
}

__global__ __launch_bounds__(256)
void f32_to_h_kernel(const float* __restrict__ src, __half* __restrict__ dst, size_t n4) {
    size_t i = (size_t)blockIdx.x * 256 + threadIdx.x;
    if (i < n4) {
        float4 v = ((const float4*)src)[i];
        __half2 a = __floats2half2_rn(v.x, v.y);
        __half2 b = __floats2half2_rn(v.z, v.w);
        ((__half2*)dst)[i * 2 + 0] = a;
        ((__half2*)dst)[i * 2 + 1] = b;
    }
}

// ---------------- launch ----------------
extern "C" void kernel_launch(void* const* d_in, const int* in_sizes, int n_in,
                              void* d_out, int out_size) {
    const float* h    = (const float*)d_in[0];
    const float* mask = (const float*)d_in[1];
    const float* w1   = (const float*)d_in[2];
    const float* b1   = (const float*)d_in[3];
    const float* w2   = (const float*)d_in[4];
    const float* b2   = (const float*)d_in[5];
    const float* g1   = (const float*)d_in[6];
    const float* be1  = (const float*)d_in[7];
    const float* g2   = (const float*)d_in[8];
    const float* be2  = (const float*)d_in[9];
    float* out = (float*)d_out;

    float *scores, *attn, *h1, *f2;
    __half *probs, *h1h, *f1, *hh, *hT, *w1T, *w2T;
    cudaGetSymbolAddress((void**)&scores, g_scores);
    cudaGetSymbolAddress((void**)&probs, g_probs);
    cudaGetSymbolAddress((void**)&attn, g_attn);
    cudaGetSymbolAddress((void**)&h1, g_h1);
    cudaGetSymbolAddress((void**)&h1h, g_h1h);
    cudaGetSymbolAddress((void**)&f1, g_f1);
    cudaGetSymbolAddress((void**)&f2, g_f2);
    cudaGetSymbolAddress((void**)&hh, g_hh);
    cudaGetSymbolAddress((void**)&hT, g_hT);
    cudaGetSymbolAddress((void**)&w1T, g_w1T);
    cudaGetSymbolAddress((void**)&w2T, g_w2T);

    cudaFuncSetAttribute(mma_gemm<0, float>, cudaFuncAttributeMaxDynamicSharedMemorySize, DYN_SMEM);
    cudaFuncSetAttribute(mma_gemm<1, __half>, cudaFuncAttributeMaxDynamicSharedMemorySize, DYN_SMEM);
    cudaFuncSetAttribute(mma_gemm<2, float>, cudaFuncAttributeMaxDynamicSharedMemorySize, DYN_SMEM);

    const size_t SD = (size_t)S_ * D_;
    const size_t SS = (size_t)S_ * S_;

    // operand prep: fp16 conversion + K-major transposes
    f32_to_h_kernel<<<(B_ * SD / 4 + 255) / 256, 256>>>(h, hh, B_ * SD / 4);
    transpose_h_kernel<<<dim3(D_ / 32, S_ / 32, B_), 256>>>(h, hT, S_, D_, SD, SD);
    transpose_h_kernel<<<dim3(F_ / 32, D_ / 32, 1), 256>>>(w1, w1T, D_, F_, 0, 0);
    transpose_h_kernel<<<dim3(D_ / 32, F_ / 32, 1), 256>>>(w2, w2T, F_, D_, 0, 0);

    // 1) scores = (h @ h^T) / 32
    mma_gemm<0, float><<<dim3(S_ / 128, S_ / 128, B_), 256, DYN_SMEM>>>(
        hh, hh, nullptr, scores, S_, S_, D_, SD, SD, SS, 0.03125f);

    // 2) softmax (+mask) -> fp16 probs
    softmax_kernel<<<B_ * S_, 256>>>(scores, mask, probs);

    // 3) attn = P @ h
    mma_gemm<0, float><<<dim3(D_ / 128, S_ / 128, B_), 256, DYN_SMEM>>>(
        probs, hT, nullptr, attn, S_, D_, S_, SS, SD, SD, 1.0f);

    // 4) h1 = LN1(h + attn)  (+ fp16 twin)
    add_ln_kernel<<<B_ * S_, 256>>>(attn, h, g1, be1, h1, h1h);

    // 5) f1 = GELU(h1 @ w1 + b1)  -> fp16
    mma_gemm<1, __half><<<dim3(F_ / 128, (B_ * S_) / 128, 1), 256, DYN_SMEM>>>(
        h1h, w1T, b1, f1, B_ * S_, F_, D_, 0, 0, 0, 1.0f);

    // 6) f2 = f1 @ w2 + b2
    mma_gemm<2, float><<<dim3(D_ / 128, (B_ * S_) / 128, 1), 256, DYN_SMEM>>>(
        f1, w2T, b2, f2, B_ * S_, D_, F_, 0, 0, 0, 1.0f);

    // 7) out = LN2(h1 + f2)
    add_ln_kernel<<<B_ * S_, 256>>>(f2, h1, g2, be2, out, nullptr);
}

// round 8
// speedup vs baseline: 6.3770x; 1.1642x over previous
#include <cuda_runtime.h>
#include <cuda_fp16.h>
#include <math.h>
#include <stdint.h>

#define B_ 4
#define S_ 2048
#define D_ 1024
#define F_ 4096

// ---------------- scratch (static device globals; no allocs) ----------------
__device__ __half g_scores[(size_t)B_ * S_ * S_];   // 32 MB fp16
__device__ __half g_probs [(size_t)B_ * S_ * S_];   // 32 MB fp16
__device__ float  g_attn  [(size_t)B_ * S_ * D_];   // 32 MB
__device__ float  g_h1    [(size_t)B_ * S_ * D_];   // 32 MB fp32 residual
__device__ __half g_h1h   [(size_t)B_ * S_ * D_];   // 16 MB fp16 twin
__device__ __half g_f1    [(size_t)B_ * S_ * F_];   // 64 MB fp16
__device__ float  g_f2    [(size_t)B_ * S_ * D_];   // 32 MB
__device__ __half g_hh    [(size_t)B_ * S_ * D_];   // 16 MB h as fp16
__device__ __half g_hT    [(size_t)B_ * D_ * S_];   // 16 MB h^T fp16
__device__ __half g_w1T   [(size_t)F_ * D_];        // 8 MB
__device__ __half g_w2T   [(size_t)D_ * F_];        // 8 MB

// ---------------- helpers ----------------
__device__ __forceinline__ uint32_t smem_u32(const void* p) {
    return (uint32_t)__cvta_generic_to_shared(p);
}

#define CP_ASYNC16(sa, ga) \
    asm volatile("cp.async.cg.shared.global [%0], [%1], 16;" :: "r"(sa), "l"(ga))
#define CP_COMMIT() asm volatile("cp.async.commit_group;" ::: "memory")
#define CP_WAIT2()  asm volatile("cp.async.wait_group 2;" ::: "memory")

#define LDMATRIX_X4(r0, r1, r2, r3, addr)                                    \
    asm volatile("ldmatrix.sync.aligned.m8n8.x4.shared.b16 {%0,%1,%2,%3}, [%4];" \
                 : "=r"(r0), "=r"(r1), "=r"(r2), "=r"(r3) : "r"(addr))

// fp16 m16n8k16 MMA, fp32 accumulate
__device__ __forceinline__ void mma_f16(float* d, const uint32_t* a, const uint32_t* b) {
    asm volatile(
        "mma.sync.aligned.m16n8k16.row.col.f32.f16.f16.f32 "
        "{%0,%1,%2,%3}, {%4,%5,%6,%7}, {%8,%9}, {%0,%1,%2,%3};"
        : "+f"(d[0]), "+f"(d[1]), "+f"(d[2]), "+f"(d[3])
        : "r"(a[0]), "r"(a[1]), "r"(a[2]), "r"(a[3]), "r"(b[0]), "r"(b[1]));
}

// ---------------- fp16 GEMM ----------------
// C[M,N] = A[M,K] * B_op[N,K]^T, fp16 K-major operands, fp32 accum.
// CTA tile 128x128, 128 threads (4 warps, 2x2 grid of 64x64 warp tiles),
// K-chunk 32 halfs, 4-stage cp.async ring, one barrier/chunk, 2 CTAs/SM.
// Fragments via ldmatrix.x4; pitch 80B -> conflict-free.
// EPI: 0 = *alpha ; 1 = +bias, exact GELU ; 2 = +bias.
#define KC 32
#define ROW_BYTES 80
#define T_TILE_BYTES (128 * ROW_BYTES)        // 10240
#define STAGE_BYTES (2 * T_TILE_BYTES)        // 20480 (A + B)
#define NSTAGE 4
#define DYN_SMEM (NSTAGE * STAGE_BYTES)       // 81920 -> 2 CTAs = 160 KB/SM

__device__ __forceinline__ void load_tile(uint32_t sbase, const __half* __restrict__ Arow,
                                          const __half* __restrict__ Brow,
                                          int K, int kc, int tid) {
    const int r0 = tid >> 2;            // 0..31
    const int c  = tid & 3;             // 16B chunk (8 halfs)
    const __half* Ap = Arow + (size_t)kc * KC + c * 8;
    const __half* Bp = Brow + (size_t)kc * KC + c * 8;
#pragma unroll
    for (int i = 0; i < 4; i++) {
        int r = r0 + i * 32;
        CP_ASYNC16(sbase + r * ROW_BYTES + c * 16, Ap + (size_t)r * K);
    }
    uint32_t bb = sbase + T_TILE_BYTES;
#pragma unroll
    for (int i = 0; i < 4; i++) {
        int r = r0 + i * 32;
        CP_ASYNC16(bb + r * ROW_BYTES + c * 16, Bp + (size_t)r * K);
    }
}

template <int EPI, typename OutT>
__global__ __launch_bounds__(128, 2)
void mma_gemm(const __half* __restrict__ A, const __half* __restrict__ Bm,
              const float* __restrict__ bias, OutT* __restrict__ C,
              int M, int N, int K, size_t sA, size_t sB, size_t sC, float alpha) {
    extern __shared__ char dsm[];
    const int tid = threadIdx.x, wid = tid >> 5, lane = tid & 31;
    const int z = blockIdx.z;
    A  += (size_t)z * sA;
    Bm += (size_t)z * sB;
    C  += (size_t)z * sC;
    const int m0 = blockIdx.y * 128;
    const int n0 = blockIdx.x * 128;
    const __half* Arow = A + (size_t)m0 * K;
    const __half* Brow = Bm + (size_t)n0 * K;
    const int NC = K / KC;

    // warp tile 64x64: warps 2(m) x 2(n)
    const int wm = (wid & 1) * 64;
    const int wn = (wid >> 1) * 64;
    const int gq = lane >> 2;
    const int tg = lane & 3;

    float acc[4][8][4];
#pragma unroll
    for (int g = 0; g < 4; g++)
#pragma unroll
        for (int j = 0; j < 8; j++)
#pragma unroll
            for (int q = 0; q < 4; q++) acc[g][j][q] = 0.0f;

    const uint32_t s0 = smem_u32(dsm);
    // ldmatrix lane-address offsets (within a stage)
    const uint32_t a_off = (uint32_t)(wm + (lane & 15)) * ROW_BYTES + ((lane >> 4) & 1) * 16;
    const uint32_t b_off = T_TILE_BYTES +
        (uint32_t)(wn + (lane & 7) + ((lane >> 4) & 1) * 8) * ROW_BYTES + ((lane >> 3) & 1) * 16;

#pragma unroll
    for (int s = 0; s < NSTAGE - 1; s++) {
        load_tile(s0 + s * STAGE_BYTES, Arow, Brow, K, s, tid);
        CP_COMMIT();
    }

    for (int k = 0; k < NC; k++) {
        const int buf = k & (NSTAGE - 1);
        CP_WAIT2();
        __syncthreads();
        if (k + NSTAGE - 1 < NC)
            load_tile(s0 + ((k + NSTAGE - 1) & (NSTAGE - 1)) * STAGE_BYTES,
                      Arow, Brow, K, k + NSTAGE - 1, tid);
        CP_COMMIT();

        const uint32_t sb = s0 + buf * STAGE_BYTES;
        const uint32_t aab = sb + a_off;
        const uint32_t bab = sb + b_off;

#pragma unroll
        for (int ks = 0; ks < 2; ks++) {      // two k16 steps per chunk
            const uint32_t kbb = ks * 32;     // 16 halfs = 32B
            uint32_t afr[4][4];
#pragma unroll
            for (int g = 0; g < 4; g++)
                LDMATRIX_X4(afr[g][0], afr[g][1], afr[g][2], afr[g][3],
                            aab + g * (16 * ROW_BYTES) + kbb);
            uint32_t bfr[8][2];
#pragma unroll
            for (int p = 0; p < 4; p++) {
                uint32_t t0, t1, t2, t3;
                LDMATRIX_X4(t0, t1, t2, t3, bab + p * (16 * ROW_BYTES) + kbb);
                bfr[2 * p][0] = t0; bfr[2 * p][1] = t1;
                bfr[2 * p + 1][0] = t2; bfr[2 * p + 1][1] = t3;
            }
#pragma unroll
            for (int g = 0; g < 4; g++)
#pragma unroll
                for (int j = 0; j < 8; j++) mma_f16(acc[g][j], afr[g], bfr[j]);
        }
    }

    // epilogue
#pragma unroll
    for (int g = 0; g < 4; g++) {
        const int rb = m0 + wm + g * 16 + gq;
#pragma unroll
        for (int j = 0; j < 8; j++) {
            const int cb = n0 + wn + j * 8 + tg * 2;
            float bx = 0.f, by = 0.f;
            if (EPI != 0) { bx = bias[cb]; by = bias[cb + 1]; }
#pragma unroll
            for (int hh = 0; hh < 2; hh++) {   // rows gq, gq+8
                float x = acc[g][j][hh * 2 + 0];
                float y = acc[g][j][hh * 2 + 1];
                if (EPI == 0) {
                    x *= alpha; y *= alpha;
                } else {
                    x += bx; y += by;
                    if (EPI == 1) {
                        x = 0.5f * x * (1.0f + erff(x * 0.7071067811865475f));
                        y = 0.5f * y * (1.0f + erff(y * 0.7071067811865475f));
                    }
                }
                OutT* cp = C + (size_t)(rb + hh * 8) * N + cb;
                if (sizeof(OutT) == 2) {
                    *(__half2*)cp = __floats2half2_rn(x, y);
                } else {
                    *(float2*)cp = make_float2(x, y);
                }
            }
        }
    }
}

// ---------------- pointwise / reduction kernels ----------------
__device__ __forceinline__ float warpSum(float v) {
#pragma unroll
    for (int o = 16; o > 0; o >>= 1) v += __shfl_xor_sync(0xFFFFFFFFu, v, o);
    return v;
}
__device__ __forceinline__ float warpMax(float v) {
#pragma unroll
    for (int o = 16; o > 0; o >>= 1) v = fmaxf(v, __shfl_xor_sync(0xFFFFFFFFu, v, o));
    return v;
}
__device__ __forceinline__ float blockSum(float v) {
    __shared__ float sh[9];
    __syncthreads();
    int lane = threadIdx.x & 31, w = threadIdx.x >> 5;
    v = warpSum(v);
    if (lane == 0) sh[w] = v;
    __syncthreads();
    if (w == 0) {
        float x = (lane < 8) ? sh[lane] : 0.0f;
        x = warpSum(x);
        if (lane == 0) sh[8] = x;
    }
    __syncthreads();
    return sh[8];
}
__device__ __forceinline__ float blockMax(float v) {
    __shared__ float sh[9];
    __syncthreads();
    int lane = threadIdx.x & 31, w = threadIdx.x >> 5;
    v = warpMax(v);
    if (lane == 0) sh[w] = v;
    __syncthreads();
    if (w == 0) {
        float x = (lane < 8) ? sh[lane] : -INFINITY;
        x = warpMax(x);
        if (lane == 0) sh[8] = x;
    }
    __syncthreads();
    return sh[8];
}

__global__ __launch_bounds__(256)
void softmax_kernel(const __half* __restrict__ scores, const float* __restrict__ mask,
                    __half* __restrict__ probs) {
    const int row = blockIdx.x;
    const int b = row / S_;
    const __half* p = scores + (size_t)row * S_;
    __half* po = probs + (size_t)row * S_;
    const float* mk = mask + (size_t)b * S_;
    const int t = threadIdx.x;
    float v[8];
    float mx = -INFINITY;
#pragma unroll
    for (int i = 0; i < 8; i++) {
        int k = t + i * 256;
        v[i] = __half2float(p[k]) + mk[k];
        mx = fmaxf(mx, v[i]);
    }
    mx = blockMax(mx);
    float s = 0.0f;
#pragma unroll
    for (int i = 0; i < 8; i++) {
        v[i] = __expf(v[i] - mx);
        s += v[i];
    }
    s = blockSum(s);
    float inv = 1.0f / s;
#pragma unroll
    for (int i = 0; i < 8; i++) po[t + i * 256] = __float2half_rn(v[i] * inv);
}

__global__ __launch_bounds__(256)
void add_ln_kernel(const float* __restrict__ x, const float* __restrict__ res,
                   const float* __restrict__ gamma, const float* __restrict__ beta,
                   float* __restrict__ out, __half* __restrict__ out_h) {
    const int row = blockIdx.x;
    const float* px = x + (size_t)row * D_;
    const float* pr = res + (size_t)row * D_;
    float* po = out + (size_t)row * D_;
    const int t = threadIdx.x;
    float v[4];
    float s = 0.0f, s2 = 0.0f;
#pragma unroll
    for (int i = 0; i < 4; i++) {
        int k = t + i * 256;
        v[i] = px[k] + pr[k];
        s += v[i];
        s2 += v[i] * v[i];
    }
    s = blockSum(s);
    s2 = blockSum(s2);
    const float mu = s * (1.0f / D_);
    const float var = s2 * (1.0f / D_) - mu * mu;
    const float inv = rsqrtf(var + 1e-5f);
#pragma unroll
    for (int i = 0; i < 4; i++) {
        int k = t + i * 256;
        float y = (v[i] - mu) * inv * gamma[k] + beta[k];
        po[k] = y;
        if (out_h) out_h[(size_t)row * D_ + k] = __float2half_rn(y);
    }
}

__global__ __launch_bounds__(256)
void transpose_h_kernel(const float* __restrict__ src, __half* __restrict__ dst,
                        int R, int C, size_t sS, size_t sD) {
    __shared__ float t[32][33];
    src += (size_t)blockIdx.z * sS;
    dst += (size_t)blockIdx.z * sD;
    const int c0 = blockIdx.x * 32, r0 = blockIdx.y * 32;
    const int x = threadIdx.x & 31, y = (threadIdx.x >> 5) * 4;
#pragma unroll
    for (int i = 0; i < 4; i++)
        t[y + i][x] = src[(size_t)(r0 + y + i) * C + c0 + x];
    __syncthreads();
#pragma unroll
    for (int i = 0; i < 4; i++)
        dst[(size_t)(c0 + y + i) * R + r0 + x] = __float2half_rn(t[x][y + i]);
}

__global__ __launch_bounds__(256)
void f32_to_h_kernel(const float* __restrict__ src, __half* __restrict__ dst, size_t n4) {
    size_t i = (size_t)blockIdx.x * 256 + threadIdx.x;
    if (i < n4) {
        float4 v = ((const float4*)src)[i];
        ((__half2*)dst)[i * 2 + 0] = __floats2half2_rn(v.x, v.y);
        ((__half2*)dst)[i * 2 + 1] = __floats2half2_rn(v.z, v.w);
    }
}

// ---------------- launch ----------------
extern "C" void kernel_launch(void* const* d_in, const int* in_sizes, int n_in,
                              void* d_out, int out_size) {
    const float* h    = (const float*)d_in[0];
    const float* mask = (const float*)d_in[1];
    const float* w1   = (const float*)d_in[2];
    const float* b1   = (const float*)d_in[3];
    const float* w2   = (const float*)d_in[4];
    const float* b2   = (const float*)d_in[5];
    const float* g1   = (const float*)d_in[6];
    const float* be1  = (const float*)d_in[7];
    const float* g2   = (const float*)d_in[8];
    const float* be2  = (const float*)d_in[9];
    float* out = (float*)d_out;

    float *attn, *h1, *f2;
    __half *scores, *probs, *h1h, *f1, *hh, *hT, *w1T, *w2T;
    cudaGetSymbolAddress((void**)&scores, g_scores);
    cudaGetSymbolAddress((void**)&probs, g_probs);
    cudaGetSymbolAddress((void**)&attn, g_attn);
    cudaGetSymbolAddress((void**)&h1, g_h1);
    cudaGetSymbolAddress((void**)&h1h, g_h1h);
    cudaGetSymbolAddress((void**)&f1, g_f1);
    cudaGetSymbolAddress((void**)&f2, g_f2);
    cudaGetSymbolAddress((void**)&hh, g_hh);
    cudaGetSymbolAddress((void**)&hT, g_hT);
    cudaGetSymbolAddress((void**)&w1T, g_w1T);
    cudaGetSymbolAddress((void**)&w2T, g_w2T);

    cudaFuncSetAttribute(mma_gemm<0, __half>, cudaFuncAttributeMaxDynamicSharedMemorySize, DYN_SMEM);
    cudaFuncSetAttribute(mma_gemm<0, float>,  cudaFuncAttributeMaxDynamicSharedMemorySize, DYN_SMEM);
    cudaFuncSetAttribute(mma_gemm<1, __half>, cudaFuncAttributeMaxDynamicSharedMemorySize, DYN_SMEM);
    cudaFuncSetAttribute(mma_gemm<2, float>,  cudaFuncAttributeMaxDynamicSharedMemorySize, DYN_SMEM);

    const size_t SD = (size_t)S_ * D_;
    const size_t SS = (size_t)S_ * S_;

    // operand prep: fp16 conversion + K-major transposes
    f32_to_h_kernel<<<(B_ * SD / 4 + 255) / 256, 256>>>(h, hh, B_ * SD / 4);
    transpose_h_kernel<<<dim3(D_ / 32, S_ / 32, B_), 256>>>(h, hT, S_, D_, SD, SD);
    transpose_h_kernel<<<dim3(F_ / 32, D_ / 32, 1), 256>>>(w1, w1T, D_, F_, 0, 0);
    transpose_h_kernel<<<dim3(D_ / 32, F_ / 32, 1), 256>>>(w2, w2T, F_, D_, 0, 0);

    // 1) scores = (h @ h^T) / 32  -> fp16
    mma_gemm<0, __half><<<dim3(S_ / 128, S_ / 128, B_), 128, DYN_SMEM>>>(
        hh, hh, nullptr, scores, S_, S_, D_, SD, SD, SS, 0.03125f);

    // 2) softmax (+mask) -> fp16 probs
    softmax_kernel<<<B_ * S_, 256>>>(scores, mask, probs);

    // 3) attn = P @ h
    mma_gemm<0, float><<<dim3(D_ / 128, S_ / 128, B_), 128, DYN_SMEM>>>(
        probs, hT, nullptr, attn, S_, D_, S_, SS, SD, SD, 1.0f);

    // 4) h1 = LN1(h + attn)  (+ fp16 twin)
    add_ln_kernel<<<B_ * S_, 256>>>(attn, h, g1, be1, h1, h1h);

    // 5) f1 = GELU(h1 @ w1 + b1)  -> fp16
    mma_gemm<1, __half><<<dim3(F_ / 128, (B_ * S_) / 128, 1), 128, DYN_SMEM>>>(
        h1h, w1T, b1, f1, B_ * S_, F_, D_, 0, 0, 0, 1.0f);

    // 6) f2 = f1 @ w2 + b2
    mma_gemm<2, float><<<dim3(D_ / 128, (B_ * S_) / 128, 1), 128, DYN_SMEM>>>(
        f1, w2T, b2, f2, B_ * S_, D_, F_, 0, 0, 0, 1.0f);

    // 7) out = LN2(h1 + f2)
    add_ln_kernel<<<B_ * S_, 256>>>(f2, h1, g2, be2, out, nullptr);
}

// round 9
// speedup vs baseline: 6.6830x; 1.0480x over previous
#include <cuda_runtime.h>
#include <cuda_fp16.h>
#include <math.h>
#include <stdint.h>

#define B_ 4
#define S_ 2048
#define D_ 1024
#define F_ 4096

// ---------------- scratch (static device globals; no allocs) ----------------
__device__ __half g_scores[(size_t)B_ * S_ * S_];   // 32 MB fp16
__device__ __half g_probs [(size_t)B_ * S_ * S_];   // 32 MB fp16
__device__ float  g_attn  [(size_t)B_ * S_ * D_];   // 32 MB
__device__ float  g_h1    [(size_t)B_ * S_ * D_];   // 32 MB fp32 residual
__device__ __half g_h1h   [(size_t)B_ * S_ * D_];   // 16 MB fp16 twin
__device__ __half g_f1    [(size_t)B_ * S_ * F_];   // 64 MB fp16
__device__ float  g_f2    [(size_t)B_ * S_ * D_];   // 32 MB
__device__ __half g_hh    [(size_t)B_ * S_ * D_];   // 16 MB h as fp16
__device__ __half g_hT    [(size_t)B_ * D_ * S_];   // 16 MB h^T fp16
__device__ __half g_w1T   [(size_t)F_ * D_];        // 8 MB
__device__ __half g_w2T   [(size_t)D_ * F_];        // 8 MB

// ---------------- helpers ----------------
__device__ __forceinline__ uint32_t smem_u32(const void* p) {
    return (uint32_t)__cvta_generic_to_shared(p);
}

#define CP_ASYNC16(sa, ga) \
    asm volatile("cp.async.cg.shared.global [%0], [%1], 16;" :: "r"(sa), "l"(ga))
#define CP_COMMIT() asm volatile("cp.async.commit_group;" ::: "memory")
#define CP_WAIT2()  asm volatile("cp.async.wait_group 2;" ::: "memory")

#define LDMATRIX_X4(r0, r1, r2, r3, addr)                                    \
    asm volatile("ldmatrix.sync.aligned.m8n8.x4.shared.b16 {%0,%1,%2,%3}, [%4];" \
                 : "=r"(r0), "=r"(r1), "=r"(r2), "=r"(r3) : "r"(addr))

__device__ __forceinline__ void mma_f16(float* d, const uint32_t* a, const uint32_t* b) {
    asm volatile(
        "mma.sync.aligned.m16n8k16.row.col.f32.f16.f16.f32 "
        "{%0,%1,%2,%3}, {%4,%5,%6,%7}, {%8,%9}, {%0,%1,%2,%3};"
        : "+f"(d[0]), "+f"(d[1]), "+f"(d[2]), "+f"(d[3])
        : "r"(a[0]), "r"(a[1]), "r"(a[2]), "r"(a[3]), "r"(b[0]), "r"(b[1]));
}

// ---------------- shared GEMM machinery ----------------
#define KC 32
#define ROW_BYTES 80
#define T_TILE_BYTES (128 * ROW_BYTES)        // 10240
#define STAGE_BYTES (2 * T_TILE_BYTES)        // 20480 (A + B)
#define NSTAGE 4
#define DYN_SMEM (NSTAGE * STAGE_BYTES)       // 81920 -> 2 CTAs = 160 KB/SM

__device__ __forceinline__ void load_tile(uint32_t sbase, const __half* __restrict__ Arow,
                                          const __half* __restrict__ Brow,
                                          int K, int kc, int tid) {
    const int r0 = tid >> 2;
    const int c  = tid & 3;
    const __half* Ap = Arow + (size_t)kc * KC + c * 8;
    const __half* Bp = Brow + (size_t)kc * KC + c * 8;
#pragma unroll
    for (int i = 0; i < 4; i++) {
        int r = r0 + i * 32;
        CP_ASYNC16(sbase + r * ROW_BYTES + c * 16, Ap + (size_t)r * K);
    }
    uint32_t bb = sbase + T_TILE_BYTES;
#pragma unroll
    for (int i = 0; i < 4; i++) {
        int r = r0 + i * 32;
        CP_ASYNC16(bb + r * ROW_BYTES + c * 16, Bp + (size_t)r * K);
    }
}

// Runs the full pipelined mainloop for one 128x128 tile; acc[4][8][4] filled.
__device__ __forceinline__ void gemm_mainloop(char* dsm, const __half* Arow,
                                              const __half* Brow, int K, int tid,
                                              int wm, int wn, float acc[4][8][4]) {
    const uint32_t s0 = smem_u32(dsm);
    const int lane = tid & 31;
    const uint32_t a_off = (uint32_t)(wm + (lane & 15)) * ROW_BYTES + ((lane >> 4) & 1) * 16;
    const uint32_t b_off = T_TILE_BYTES +
        (uint32_t)(wn + (lane & 7) + ((lane >> 4) & 1) * 8) * ROW_BYTES + ((lane >> 3) & 1) * 16;
    const int NC = K / KC;

#pragma unroll
    for (int s = 0; s < NSTAGE - 1; s++) {
        load_tile(s0 + s * STAGE_BYTES, Arow, Brow, K, s, tid);
        CP_COMMIT();
    }
    for (int k = 0; k < NC; k++) {
        const int buf = k & (NSTAGE - 1);
        CP_WAIT2();
        __syncthreads();
        if (k + NSTAGE - 1 < NC)
            load_tile(s0 + ((k + NSTAGE - 1) & (NSTAGE - 1)) * STAGE_BYTES,
                      Arow, Brow, K, k + NSTAGE - 1, tid);
        CP_COMMIT();

        const uint32_t sb = s0 + buf * STAGE_BYTES;
        const uint32_t aab = sb + a_off;
        const uint32_t bab = sb + b_off;
#pragma unroll
        for (int ks = 0; ks < 2; ks++) {
            const uint32_t kbb = ks * 32;
            uint32_t afr[4][4];
#pragma unroll
            for (int g = 0; g < 4; g++)
                LDMATRIX_X4(afr[g][0], afr[g][1], afr[g][2], afr[g][3],
                            aab + g * (16 * ROW_BYTES) + kbb);
            uint32_t bfr[8][2];
#pragma unroll
            for (int p = 0; p < 4; p++) {
                uint32_t t0, t1, t2, t3;
                LDMATRIX_X4(t0, t1, t2, t3, bab + p * (16 * ROW_BYTES) + kbb);
                bfr[2 * p][0] = t0; bfr[2 * p][1] = t1;
                bfr[2 * p + 1][0] = t2; bfr[2 * p + 1][1] = t3;
            }
#pragma unroll
            for (int g = 0; g < 4; g++)
#pragma unroll
                for (int j = 0; j < 8; j++) mma_f16(acc[g][j], afr[g], bfr[j]);
        }
    }
}

// ---------------- generic fp16 GEMM (EPI: 0=*alpha, 1=+bias GELU, 2=+bias) ----
template <int EPI, typename OutT>
__global__ __launch_bounds__(128, 2)
void mma_gemm(const __half* __restrict__ A, const __half* __restrict__ Bm,
              const float* __restrict__ bias, OutT* __restrict__ C,
              int M, int N, int K, size_t sA, size_t sB, size_t sC, float alpha) {
    extern __shared__ char dsm[];
    const int tid = threadIdx.x, wid = tid >> 5, lane = tid & 31;
    const int z = blockIdx.z;
    A  += (size_t)z * sA;
    Bm += (size_t)z * sB;
    C  += (size_t)z * sC;
    const int m0 = blockIdx.y * 128;
    const int n0 = blockIdx.x * 128;
    const int wm = (wid & 1) * 64;
    const int wn = (wid >> 1) * 64;
    const int gq = lane >> 2;
    const int tg = lane & 3;

    float acc[4][8][4];
#pragma unroll
    for (int g = 0; g < 4; g++)
#pragma unroll
        for (int j = 0; j < 8; j++)
#pragma unroll
            for (int q = 0; q < 4; q++) acc[g][j][q] = 0.0f;

    gemm_mainloop(dsm, A + (size_t)m0 * K, Bm + (size_t)n0 * K, K, tid, wm, wn, acc);

#pragma unroll
    for (int g = 0; g < 4; g++) {
        const int rb = m0 + wm + g * 16 + gq;
#pragma unroll
        for (int j = 0; j < 8; j++) {
            const int cb = n0 + wn + j * 8 + tg * 2;
            float bx = 0.f, by = 0.f;
            if (EPI != 0) { bx = bias[cb]; by = bias[cb + 1]; }
#pragma unroll
            for (int hh = 0; hh < 2; hh++) {
                float x = acc[g][j][hh * 2 + 0];
                float y = acc[g][j][hh * 2 + 1];
                if (EPI == 0) {
                    x *= alpha; y *= alpha;
                } else {
                    x += bx; y += by;
                    if (EPI == 1) {
                        x = 0.5f * x * (1.0f + erff(x * 0.7071067811865475f));
                        y = 0.5f * y * (1.0f + erff(y * 0.7071067811865475f));
                    }
                }
                OutT* cp = C + (size_t)(rb + hh * 8) * N + cb;
                if (sizeof(OutT) == 2) {
                    *(__half2*)cp = __floats2half2_rn(x, y);
                } else {
                    *(float2*)cp = make_float2(x, y);
                }
            }
        }
    }
}

// ---------------- symmetric scores GEMM: C = (A A^T) * alpha, fp16 out -------
// Upper-triangular tiles only; mirror tile written via SMEM transpose staging.
#define NT (S_ / 128)     // 16 tiles per side
#define NTRI (NT * (NT + 1) / 2)   // 136
#define TP 136            // staging pitch (halfs)

__global__ __launch_bounds__(128, 2)
void mma_gemm_sym(const __half* __restrict__ A, __half* __restrict__ C,
                  int K, size_t sA, size_t sC, float alpha) {
    extern __shared__ char dsm[];
    const int tid = threadIdx.x, wid = tid >> 5, lane = tid & 31;
    const int z = blockIdx.z;
    A += (size_t)z * sA;
    C += (size_t)z * sC;

    // linear triangular index -> (i, j), i <= j
    int ti = blockIdx.x, i = 0;
    while (ti >= NT - i) { ti -= NT - i; i++; }
    const int j = i + ti;
    const int m0 = i * 128, n0 = j * 128;

    const int wm = (wid & 1) * 64;
    const int wn = (wid >> 1) * 64;
    const int gq = lane >> 2;
    const int tg = lane & 3;

    float acc[4][8][4];
#pragma unroll
    for (int g = 0; g < 4; g++)
#pragma unroll
        for (int jj = 0; jj < 8; jj++)
#pragma unroll
            for (int q = 0; q < 4; q++) acc[g][jj][q] = 0.0f;

    gemm_mainloop(dsm, A + (size_t)m0 * K, A + (size_t)n0 * K, K, tid, wm, wn, acc);

    // stage fp16 tile in smem (pipeline smem is dead now)
    __half (*T)[TP] = (__half (*)[TP])dsm;
    __syncthreads();
#pragma unroll
    for (int g = 0; g < 4; g++) {
        const int rl = wm + g * 16 + gq;
#pragma unroll
        for (int jj = 0; jj < 8; jj++) {
            const int cl = wn + jj * 8 + tg * 2;
#pragma unroll
            for (int hh = 0; hh < 2; hh++) {
                __half2 hv = __floats2half2_rn(acc[g][jj][hh * 2] * alpha,
                                               acc[g][jj][hh * 2 + 1] * alpha);
                *(__half2*)&T[rl + hh * 8][cl] = hv;
            }
        }
    }
    __syncthreads();

    // direct tile write: 2048 16B-chunks, coalesced
    for (int it = 0; it < 16; it++) {
        int id = tid + it * 128;
        int r = id >> 4, c8 = (id & 15) * 8;
        *(uint4*)(C + (size_t)(m0 + r) * S_ + n0 + c8) = *(uint4*)&T[r][c8];
    }
    // mirror tile write (j,i): mirror[mr][mc] = T[mc][mr]
    if (i != j) {
        for (int it = 0; it < 16; it++) {
            int id = tid + it * 128;
            int mr = id >> 4, mc8 = (id & 15) * 8;
            __half v[8];
#pragma unroll
            for (int q = 0; q < 8; q++) v[q] = T[mc8 + q][mr];
            *(uint4*)(C + (size_t)(n0 + mr) * S_ + m0 + mc8) = *(uint4*)v;
        }
    }
}

// ---------------- pointwise / reduction kernels ----------------
__device__ __forceinline__ float warpSum(float v) {
#pragma unroll
    for (int o = 16; o > 0; o >>= 1) v += __shfl_xor_sync(0xFFFFFFFFu, v, o);
    return v;
}
__device__ __forceinline__ float warpMax(float v) {
#pragma unroll
    for (int o = 16; o > 0; o >>= 1) v = fmaxf(v, __shfl_xor_sync(0xFFFFFFFFu, v, o));
    return v;
}
__device__ __forceinline__ float blockSum(float v) {
    __shared__ float sh[9];
    __syncthreads();
    int lane = threadIdx.x & 31, w = threadIdx.x >> 5;
    v = warpSum(v);
    if (lane == 0) sh[w] = v;
    __syncthreads();
    if (w == 0) {
        float x = (lane < 8) ? sh[lane] : 0.0f;
        x = warpSum(x);
        if (lane == 0) sh[8] = x;
    }
    __syncthreads();
    return sh[8];
}
__device__ __forceinline__ float blockMax(float v) {
    __shared__ float sh[9];
    __syncthreads();
    int lane = threadIdx.x & 31, w = threadIdx.x >> 5;
    v = warpMax(v);
    if (lane == 0) sh[w] = v;
    __syncthreads();
    if (w == 0) {
        float x = (lane < 8) ? sh[lane] : -INFINITY;
        x = warpMax(x);
        if (lane == 0) sh[8] = x;
    }
    __syncthreads();
    return sh[8];
}

__global__ __launch_bounds__(256)
void softmax_kernel(const __half* __restrict__ scores, const float* __restrict__ mask,
                    __half* __restrict__ probs) {
    const int row = blockIdx.x;
    const int b = row / S_;
    const __half* p = scores + (size_t)row * S_;
    __half* po = probs + (size_t)row * S_;
    const float* mk = mask + (size_t)b * S_;
    const int t = threadIdx.x;
    float v[8];
    float mx = -INFINITY;
#pragma unroll
    for (int i = 0; i < 8; i++) {
        int k = t + i * 256;
        v[i] = __half2float(p[k]) + mk[k];
        mx = fmaxf(mx, v[i]);
    }
    mx = blockMax(mx);
    float s = 0.0f;
#pragma unroll
    for (int i = 0; i < 8; i++) {
        v[i] = __expf(v[i] - mx);
        s += v[i];
    }
    s = blockSum(s);
    float inv = 1.0f / s;
#pragma unroll
    for (int i = 0; i < 8; i++) po[t + i * 256] = __float2half_rn(v[i] * inv);
}

__global__ __launch_bounds__(256)
void add_ln_kernel(const float* __restrict__ x, const float* __restrict__ res,
                   const float* __restrict__ gamma, const float* __restrict__ beta,
                   float* __restrict__ out, __half* __restrict__ out_h) {
    const int row = blockIdx.x;
    const float* px = x + (size_t)row * D_;
    const float* pr = res + (size_t)row * D_;
    float* po = out + (size_t)row * D_;
    const int t = threadIdx.x;
    float v[4];
    float s = 0.0f, s2 = 0.0f;
#pragma unroll
    for (int i = 0; i < 4; i++) {
        int k = t + i * 256;
        v[i] = px[k] + pr[k];
        s += v[i];
        s2 += v[i] * v[i];
    }
    s = blockSum(s);
    s2 = blockSum(s2);
    const float mu = s * (1.0f / D_);
    const float var = s2 * (1.0f / D_) - mu * mu;
    const float inv = rsqrtf(var + 1e-5f);
#pragma unroll
    for (int i = 0; i < 4; i++) {
        int k = t + i * 256;
        float y = (v[i] - mu) * inv * gamma[k] + beta[k];
        po[k] = y;
        if (out_h) out_h[(size_t)row * D_ + k] = __float2half_rn(y);
    }
}

// h -> hh (fp16 row-major) and hT (fp16 transposed), single pass over h.
__global__ __launch_bounds__(256)
void conv_and_transpose_kernel(const float* __restrict__ src, __half* __restrict__ dst,
                               __half* __restrict__ dstT, int R, int C,
                               size_t sS, size_t sD, size_t sDT) {
    __shared__ float t[32][33];
    src  += (size_t)blockIdx.z * sS;
    if (dst) dst += (size_t)blockIdx.z * sD;
    dstT += (size_t)blockIdx.z * sDT;
    const int c0 = blockIdx.x * 32, r0 = blockIdx.y * 32;
    const int x = threadIdx.x & 31, y = (threadIdx.x >> 5) * 4;
#pragma unroll
    for (int i = 0; i < 4; i++) {
        float v = src[(size_t)(r0 + y + i) * C + c0 + x];
        t[y + i][x] = v;
        if (dst) dst[(size_t)(r0 + y + i) * C + c0 + x] = __float2half_rn(v);
    }
    __syncthreads();
#pragma unroll
    for (int i = 0; i < 4; i++)
        dstT[(size_t)(c0 + y + i) * R + r0 + x] = __float2half_rn(t[x][y + i]);
}

// ---------------- launch ----------------
extern "C" void kernel_launch(void* const* d_in, const int* in_sizes, int n_in,
                              void* d_out, int out_size) {
    const float* h    = (const float*)d_in[0];
    const float* mask = (const float*)d_in[1];
    const float* w1   = (const float*)d_in[2];
    const float* b1   = (const float*)d_in[3];
    const float* w2   = (const float*)d_in[4];
    const float* b2   = (const float*)d_in[5];
    const float* g1   = (const float*)d_in[6];
    const float* be1  = (const float*)d_in[7];
    const float* g2   = (const float*)d_in[8];
    const float* be2  = (const float*)d_in[9];
    float* out = (float*)d_out;

    float *attn, *h1, *f2;
    __half *scores, *probs, *h1h, *f1, *hh, *hT, *w1T, *w2T;
    cudaGetSymbolAddress((void**)&scores, g_scores);
    cudaGetSymbolAddress((void**)&probs, g_probs);
    cudaGetSymbolAddress((void**)&attn, g_attn);
    cudaGetSymbolAddress((void**)&h1, g_h1);
    cudaGetSymbolAddress((void**)&h1h, g_h1h);
    cudaGetSymbolAddress((void**)&f1, g_f1);
    cudaGetSymbolAddress((void**)&f2, g_f2);
    cudaGetSymbolAddress((void**)&hh, g_hh);
    cudaGetSymbolAddress((void**)&hT, g_hT);
    cudaGetSymbolAddress((void**)&w1T, g_w1T);
    cudaGetSymbolAddress((void**)&w2T, g_w2T);

    cudaFuncSetAttribute(mma_gemm_sym,        cudaFuncAttributeMaxDynamicSharedMemorySize, DYN_SMEM);
    cudaFuncSetAttribute(mma_gemm<0, float>,  cudaFuncAttributeMaxDynamicSharedMemorySize, DYN_SMEM);
    cudaFuncSetAttribute(mma_gemm<1, __half>, cudaFuncAttributeMaxDynamicSharedMemorySize, DYN_SMEM);
    cudaFuncSetAttribute(mma_gemm<2, float>,  cudaFuncAttributeMaxDynamicSharedMemorySize, DYN_SMEM);

    const size_t SD = (size_t)S_ * D_;
    const size_t SS = (size_t)S_ * S_;

    // operand prep: h -> hh + hT in one pass; weight transposes
    conv_and_transpose_kernel<<<dim3(D_ / 32, S_ / 32, B_), 256>>>(
        h, hh, hT, S_, D_, SD, SD, SD);
    conv_and_transpose_kernel<<<dim3(F_ / 32, D_ / 32, 1), 256>>>(
        w1, nullptr, w1T, D_, F_, 0, 0, 0);
    conv_and_transpose_kernel<<<dim3(D_ / 32, F_ / 32, 1), 256>>>(
        w2, nullptr, w2T, F_, D_, 0, 0, 0);

    // 1) scores = (h @ h^T) / 32  -> fp16, symmetric (triangular grid + mirror)
    mma_gemm_sym<<<dim3(NTRI, 1, B_), 128, DYN_SMEM>>>(
        hh, scores, D_, SD, SS, 0.03125f);

    // 2) softmax (+mask) -> fp16 probs
    softmax_kernel<<<B_ * S_, 256>>>(scores, mask, probs);

    // 3) attn = P @ h
    mma_gemm<0, float><<<dim3(D_ / 128, S_ / 128, B_), 128, DYN_SMEM>>>(
        probs, hT, nullptr, attn, S_, D_, S_, SS, SD, SD, 1.0f);

    // 4) h1 = LN1(h + attn)  (+ fp16 twin)
    add_ln_kernel<<<B_ * S_, 256>>>(attn, h, g1, be1, h1, h1h);

    // 5) f1 = GELU(h1 @ w1 + b1)  -> fp16
    mma_gemm<1, __half><<<dim3(F_ / 128, (B_ * S_) / 128, 1), 128, DYN_SMEM>>>(
        h1h, w1T, b1, f1, B_ * S_, F_, D_, 0, 0, 0, 1.0f);

    // 6) f2 = f1 @ w2 + b2
    mma_gemm<2, float><<<dim3(D_ / 128, (B_ * S_) / 128, 1), 128, DYN_SMEM>>>(
        f1, w2T, b2, f2, B_ * S_, D_, F_, 0, 0, 0, 1.0f);

    // 7) out = LN2(h1 + f2)
    add_ln_kernel<<<B_ * S_, 256>>>(f2, h1, g2, be2, out, nullptr);
}